// round 2
// baseline (speedup 1.0000x reference)
#include <cuda_runtime.h>
#include <math.h>

// Problem constants
// B=4, T=4096, D=1024, H=8, BUCKETS=64, BSZ=64, DH=128
// BH = B*H = 32; per-(bh,bucket) tile = 64*128 = 8192 floats
#define N_TOTAL_TILES 2048          // BH * BUCKETS
#define TILE_ELEMS    8192          // BSZ * DH
#define BIG_ELEMS     16777216      // 2048 * 8192

// -------- device scratch (static globals: allocation-free, graph-safe) -----
__device__ float g_q  [BIG_ELEMS];
__device__ float g_k  [BIG_ELEMS];
__device__ float g_v  [BIG_ELEMS];
__device__ float g_kre[BIG_ELEMS];
__device__ float g_vre[BIG_ELEMS];
__device__ float g_o  [BIG_ELEMS];
__device__ float g_bkr[32 * 64 * 128];   // bucket key summaries
__device__ float g_R  [32 * 64 * 64];    // sinkhorn matrices (post tril/exp)

// ===========================================================================
// K1: QKV GEMM  C[16384,3072] = X[16384,1024] @ Wqkv[3072,1024]^T
//     epilogue scatters directly into bucketed per-head layout of q/k/v.
// ===========================================================================
__global__ void __launch_bounds__(256, 2)
qkv_gemm_kernel(const float* __restrict__ X, const float* __restrict__ W)
{
    __shared__ float As[16][128];
    __shared__ float Bs[16][128];
    const int tid = threadIdx.x;
    const int m0  = blockIdx.x * 128;
    const int n0  = blockIdx.y * 128;
    const int tr  = (tid >> 4) * 8;
    const int tc  = (tid & 15) * 8;
    float acc[8][8] = {};

    for (int k0 = 0; k0 < 1024; k0 += 16) {
        #pragma unroll
        for (int i = 0; i < 2; i++) {
            int lin = tid * 2 + i;          // 0..511
            int r   = lin >> 2;             // 0..127
            int kq  = (lin & 3) * 4;        // 0,4,8,12
            float4 a = *reinterpret_cast<const float4*>(&X[(size_t)(m0 + r) * 1024 + k0 + kq]);
            As[kq+0][r] = a.x; As[kq+1][r] = a.y; As[kq+2][r] = a.z; As[kq+3][r] = a.w;
            float4 b = *reinterpret_cast<const float4*>(&W[(size_t)(n0 + r) * 1024 + k0 + kq]);
            Bs[kq+0][r] = b.x; Bs[kq+1][r] = b.y; Bs[kq+2][r] = b.z; Bs[kq+3][r] = b.w;
        }
        __syncthreads();
        #pragma unroll
        for (int kk = 0; kk < 16; kk++) {
            float a[8], b[8];
            *(float4*)&a[0] = *(float4*)&As[kk][tr];
            *(float4*)&a[4] = *(float4*)&As[kk][tr + 4];
            *(float4*)&b[0] = *(float4*)&Bs[kk][tc];
            *(float4*)&b[4] = *(float4*)&Bs[kk][tc + 4];
            #pragma unroll
            for (int i = 0; i < 8; i++)
                #pragma unroll
                for (int j = 0; j < 8; j++)
                    acc[i][j] = fmaf(a[i], b[j], acc[i][j]);
        }
        __syncthreads();
    }

    // scatter: n-tile lies entirely in one (which, head) since boundaries are x128
    const int which = blockIdx.y >> 3;      // 0=q 1=k 2=v
    const int h     = blockIdx.y & 7;
    float* dst = (which == 0) ? g_q : (which == 1) ? g_k : g_v;
    #pragma unroll
    for (int i = 0; i < 8; i++) {
        int gm = m0 + tr + i;
        int b  = gm >> 12, t = gm & 4095;
        size_t base = ((size_t)((b * 8 + h) * 64 + (t >> 6)) * 64 + (t & 63)) * 128;
        *(float4*)&dst[base + tc]     = make_float4(acc[i][0], acc[i][1], acc[i][2], acc[i][3]);
        *(float4*)&dst[base + tc + 4] = make_float4(acc[i][4], acc[i][5], acc[i][6], acc[i][7]);
    }
}

// ===========================================================================
// K2: bucket key summaries  bkr[bh,u,dh] = sum_p k[bh,u,p,dh]
// ===========================================================================
__global__ void bucket_sum_kernel()
{
    const int bu = blockIdx.x;               // 0..2047
    const int dh = threadIdx.x;              // 0..127
    const float* src = &g_k[(size_t)bu * TILE_ELEMS];
    float s = 0.f;
    #pragma unroll
    for (int p = 0; p < 64; p++) s += src[p * 128 + dh];
    g_bkr[bu * 128 + dh] = s;
}

// ===========================================================================
// K3: sorting logits + gumbel + 5 sinkhorn iterations + tril(exp(.),-1)
//     one CTA per bh (32 CTAs, 256 threads)
// ===========================================================================
__global__ void __launch_bounds__(256)
sinkhorn_kernel(const float* __restrict__ sort_w, const float* __restrict__ noise_u)
{
    __shared__ float R[64][65];              // padded: conflict-free column walks
    const int bh  = blockIdx.x;
    const int h   = bh & 7;
    const int tid = threadIdx.x;

    // S[u][v] = sum_d bkr[bh,u,d] * sort_w[h,d,v];  R = (log(relu(S)+eps)+g)/T
    for (int i = tid; i < 4096; i += 256) {
        int u = i >> 6, v = i & 63;
        const float* br = &g_bkr[bh * 8192 + u * 128];
        const float* ew = &sort_w[h * 8192];
        float s = 0.f;
        #pragma unroll 8
        for (int d = 0; d < 128; d++) s += br[d] * ew[d * 64 + v];
        float r  = logf(fmaxf(s, 0.f) + 1e-6f);
        float nu = noise_u[bh * 4096 + i];
        float gb = -logf(-logf(nu + 1e-4f) + 1e-4f);
        R[u][v] = (r + gb) * (1.0f / 0.75f);
    }
    __syncthreads();

    const int warp = tid >> 5, lane = tid & 31;
    for (int it = 0; it < 5; it++) {
        // row logsumexp (axis=v): warp-cooperative, 2 elems/lane
        for (int r = warp; r < 64; r += 8) {
            float x0 = R[r][lane], x1 = R[r][lane + 32];
            float m = fmaxf(x0, x1);
            #pragma unroll
            for (int o = 16; o; o >>= 1) m = fmaxf(m, __shfl_xor_sync(0xffffffffu, m, o));
            float s = expf(x0 - m) + expf(x1 - m);
            #pragma unroll
            for (int o = 16; o; o >>= 1) s += __shfl_xor_sync(0xffffffffu, s, o);
            float l = m + logf(s);
            R[r][lane]      = x0 - l;
            R[r][lane + 32] = x1 - l;
        }
        __syncthreads();
        // col logsumexp (axis=u): one thread per column, conflict-free (pad 65)
        if (tid < 64) {
            float m = -INFINITY;
            for (int u2 = 0; u2 < 64; u2++) m = fmaxf(m, R[u2][tid]);
            float s = 0.f;
            for (int u2 = 0; u2 < 64; u2++) s += expf(R[u2][tid] - m);
            float l = m + logf(s);
            for (int u2 = 0; u2 < 64; u2++) R[u2][tid] -= l;
        }
        __syncthreads();
    }
    for (int i = tid; i < 4096; i += 256) {
        int u = i >> 6, v = i & 63;
        g_R[bh * 4096 + i] = (u > v) ? expf(R[u][v]) : 0.f;   // tril k=-1
    }
}

// ===========================================================================
// K4: soft permute  kre[bh,u] = sum_{v<u} R[u,v]*k[bh,v]  (and same for v)
//     one CTA per (bh,u); register-accumulated, coalesced streaming loads
// ===========================================================================
__global__ void __launch_bounds__(256, 2)
permute_kernel()
{
    __shared__ float Rs[64];
    const int blk = blockIdx.x;
    const int bh  = blk >> 6, u = blk & 63;
    const int tid = threadIdx.x;
    if (tid < 64) Rs[tid] = g_R[bh * 4096 + u * 64 + tid];
    __syncthreads();

    float ak[32] = {}, av[32] = {};
    const int dh = tid & 127;
    const int hi = tid >> 7;                  // 0/1
    const size_t bhbase = (size_t)bh * 64 * TILE_ELEMS;
    for (int v = 0; v < u; v++) {
        float r = Rs[v];
        const float* kp = &g_k[bhbase + (size_t)v * TILE_ELEMS];
        const float* vp = &g_v[bhbase + (size_t)v * TILE_ELEMS];
        #pragma unroll
        for (int i = 0; i < 32; i++) {
            int off = (2 * i + hi) * 128 + dh;
            ak[i] = fmaf(r, kp[off], ak[i]);
            av[i] = fmaf(r, vp[off], av[i]);
        }
    }
    const size_t obase = (size_t)blk * TILE_ELEMS;
    #pragma unroll
    for (int i = 0; i < 32; i++) {
        int off = (2 * i + hi) * 128 + dh;
        g_kre[obase + off] = ak[i];
        g_vre[obase + off] = av[i];
    }
}

// ===========================================================================
// K5: bucketed attention, one CTA per (bh,u). K kept transposed in smem for
//     conflict-free QK^T; V reuses K's smem region after dots are computed.
//     keys/values j<64 come from *_re, j>=64 from originals (concat implicit)
// ===========================================================================
#define ATTN_SMEM_FLOATS (8192 + 128 * 132 + 64 * 132)
#define ATTN_SMEM_BYTES  (ATTN_SMEM_FLOATS * 4)

__global__ void __launch_bounds__(256)
attn_kernel()
{
    extern __shared__ float sm[];
    float* qs = sm;                           // [64][128]
    float* kt = sm + 8192;                    // [128][132]  K^T, then V [128][132]
    float* ds = sm + 8192 + 128 * 132;        // [64][132]   dots / attn

    const int blk = blockIdx.x;
    const int tid = threadIdx.x;
    const size_t base = (size_t)blk * TILE_ELEMS;

    for (int i = tid; i < 8192; i += 256) qs[i] = g_q[base + i];
    for (int i = tid; i < 8192; i += 256) {
        int j = i >> 7, d = i & 127;
        kt[d * 132 + j] = g_kre[base + i];
    }
    for (int i = tid; i < 8192; i += 256) {
        int j = i >> 7, d = i & 127;
        kt[d * 132 + 64 + j] = g_k[base + i];
    }
    __syncthreads();

    const int tx = tid & 15, ty = tid >> 4;
    const int r0 = ty * 4, c0 = tx * 8;

    // dots = (Q @ K2^T) * d^-0.5   (d = 1024 -> scale 1/32)
    float acc[4][8] = {};
    for (int d = 0; d < 128; d++) {
        float a[4];
        #pragma unroll
        for (int i = 0; i < 4; i++) a[i] = qs[(r0 + i) * 128 + d];
        float4 b0 = *(float4*)&kt[d * 132 + c0];
        float4 b1 = *(float4*)&kt[d * 132 + c0 + 4];
        float b[8] = {b0.x, b0.y, b0.z, b0.w, b1.x, b1.y, b1.z, b1.w};
        #pragma unroll
        for (int i = 0; i < 4; i++)
            #pragma unroll
            for (int j = 0; j < 8; j++)
                acc[i][j] = fmaf(a[i], b[j], acc[i][j]);
    }
    #pragma unroll
    for (int i = 0; i < 4; i++)
        #pragma unroll
        for (int j = 0; j < 8; j++)
            ds[(r0 + i) * 132 + c0 + j] = acc[i][j] * 0.03125f;
    __syncthreads();                          // dots done: safe to overwrite kt

    // load V (re | orig) into kt region, row-major [j][e]
    for (int i = tid; i < 8192; i += 256) {
        int j = i >> 7, e = i & 127;
        kt[j * 132 + e] = g_vre[base + i];
    }
    for (int i = tid; i < 8192; i += 256) {
        int j = i >> 7, e = i & 127;
        kt[(j + 64) * 132 + e] = g_v[base + i];
    }
    // softmax rows (threads 0..63), overlapped with other warps' V loads
    if (tid < 64) {
        float m = -INFINITY;
        for (int j = 0; j < 128; j++) m = fmaxf(m, ds[tid * 132 + j]);
        float s = 0.f;
        for (int j = 0; j < 128; j++) {
            float e = expf(ds[tid * 132 + j] - m);
            ds[tid * 132 + j] = e;
            s += e;
        }
        float inv = 1.f / s;
        for (int j = 0; j < 128; j++) ds[tid * 132 + j] *= inv;
    }
    __syncthreads();

    // out = attn @ V2
    float o[4][8] = {};
    for (int j = 0; j < 128; j++) {
        float a[4];
        #pragma unroll
        for (int i = 0; i < 4; i++) a[i] = ds[(r0 + i) * 132 + j];
        float4 b0 = *(float4*)&kt[j * 132 + c0];
        float4 b1 = *(float4*)&kt[j * 132 + c0 + 4];
        float b[8] = {b0.x, b0.y, b0.z, b0.w, b1.x, b1.y, b1.z, b1.w};
        #pragma unroll
        for (int i = 0; i < 4; i++)
            #pragma unroll
            for (int jj = 0; jj < 8; jj++)
                o[i][jj] = fmaf(a[i], b[jj], o[i][jj]);
    }
    #pragma unroll
    for (int i = 0; i < 4; i++) {
        *(float4*)&g_o[base + (r0 + i) * 128 + c0]     = make_float4(o[i][0], o[i][1], o[i][2], o[i][3]);
        *(float4*)&g_o[base + (r0 + i) * 128 + c0 + 4] = make_float4(o[i][4], o[i][5], o[i][6], o[i][7]);
    }
}

// ===========================================================================
// K6: output GEMM  out[16384,1024] = O_mat @ Wout^T + b_out
//     A-tile loads gather from bucketed g_o (un-bucketize fused)
// ===========================================================================
__global__ void __launch_bounds__(256, 2)
out_gemm_kernel(const float* __restrict__ W, const float* __restrict__ bias,
                float* __restrict__ out)
{
    __shared__ float As[16][128];
    __shared__ float Bs[16][128];
    const int tid = threadIdx.x;
    const int m0  = blockIdx.x * 128;
    const int n0  = blockIdx.y * 128;
    const int tr  = (tid >> 4) * 8;
    const int tc  = (tid & 15) * 8;
    float acc[8][8] = {};

    for (int k0 = 0; k0 < 1024; k0 += 16) {
        #pragma unroll
        for (int i = 0; i < 2; i++) {
            int lin = tid * 2 + i;
            int r   = lin >> 2;
            int kq  = (lin & 3) * 4;
            int gm  = m0 + r;
            int kk  = k0 + kq;
            int b   = gm >> 12, t = gm & 4095;
            int hh  = kk >> 7, dh = kk & 127;
            size_t src = ((size_t)((b * 8 + hh) * 64 + (t >> 6)) * 64 + (t & 63)) * 128 + dh;
            float4 a = *reinterpret_cast<const float4*>(&g_o[src]);
            As[kq+0][r] = a.x; As[kq+1][r] = a.y; As[kq+2][r] = a.z; As[kq+3][r] = a.w;
            float4 bv = *reinterpret_cast<const float4*>(&W[(size_t)(n0 + r) * 1024 + kk]);
            Bs[kq+0][r] = bv.x; Bs[kq+1][r] = bv.y; Bs[kq+2][r] = bv.z; Bs[kq+3][r] = bv.w;
        }
        __syncthreads();
        #pragma unroll
        for (int kk2 = 0; kk2 < 16; kk2++) {
            float a[8], b[8];
            *(float4*)&a[0] = *(float4*)&As[kk2][tr];
            *(float4*)&a[4] = *(float4*)&As[kk2][tr + 4];
            *(float4*)&b[0] = *(float4*)&Bs[kk2][tc];
            *(float4*)&b[4] = *(float4*)&Bs[kk2][tc + 4];
            #pragma unroll
            for (int i = 0; i < 8; i++)
                #pragma unroll
                for (int j = 0; j < 8; j++)
                    acc[i][j] = fmaf(a[i], b[j], acc[i][j]);
        }
        __syncthreads();
    }

    #pragma unroll
    for (int i = 0; i < 8; i++) {
        int gm = m0 + tr + i;
        #pragma unroll
        for (int j = 0; j < 8; j++) acc[i][j] += bias[n0 + tc + j];
        *(float4*)&out[(size_t)gm * 1024 + n0 + tc]     = make_float4(acc[i][0], acc[i][1], acc[i][2], acc[i][3]);
        *(float4*)&out[(size_t)gm * 1024 + n0 + tc + 4] = make_float4(acc[i][4], acc[i][5], acc[i][6], acc[i][7]);
    }
}

// ===========================================================================
extern "C" void kernel_launch(void* const* d_in, const int* in_sizes, int n_in,
                              void* d_out, int out_size)
{
    (void)in_sizes; (void)n_in; (void)out_size;
    const float* x      = (const float*)d_in[0];   // (4,4096,1024)
    const float* w_qkv  = (const float*)d_in[1];   // (3072,1024)
    const float* sort_w = (const float*)d_in[2];   // (1,8,128,64)
    const float* w_out  = (const float*)d_in[3];   // (1024,1024)
    const float* b_out  = (const float*)d_in[4];   // (1024,)
    const float* noise  = (const float*)d_in[5];   // (32,64,64)
    float* out = (float*)d_out;

    // opt-in >48KB dynamic smem for the attention kernel (sticky per-function;
    // harmless no-op on repeat calls)
    cudaFuncSetAttribute(attn_kernel, cudaFuncAttributeMaxDynamicSharedMemorySize,
                         ATTN_SMEM_BYTES);

    qkv_gemm_kernel<<<dim3(128, 24), 256>>>(x, w_qkv);
    bucket_sum_kernel<<<2048, 128>>>();
    sinkhorn_kernel<<<32, 256>>>(sort_w, noise);
    permute_kernel<<<2048, 256>>>();
    attn_kernel<<<2048, 256, ATTN_SMEM_BYTES>>>();
    out_gemm_kernel<<<dim3(128, 8), 256>>>(w_out, b_out, out);
}

// round 6
// speedup vs baseline: 2.1323x; 2.1323x over previous
#include <cuda_runtime.h>
#include <cuda_bf16.h>
#include <math.h>
#include <stdint.h>

// Problem constants: B=4, T=4096, D=1024, H=8, BUCKETS=64, BSZ=64, DH=128
#define TILE_ELEMS    8192          // BSZ * DH
#define BIG_ELEMS     16777216      // 2048 * 8192

// -------- device scratch (static globals: allocation-free, graph-safe) -----
__device__ float g_q  [BIG_ELEMS];
__device__ float g_k  [BIG_ELEMS];
__device__ float g_v  [BIG_ELEMS];
__device__ float g_kre[BIG_ELEMS];
__device__ float g_vre[BIG_ELEMS];
__device__ float g_o  [BIG_ELEMS];
__device__ float g_bkr[32 * 64 * 128];
__device__ float g_R  [32 * 64 * 64];

// bf16 hi/lo split operands for tensor-core GEMMs
__device__ __nv_bfloat16 g_xhi [BIG_ELEMS];
__device__ __nv_bfloat16 g_xlo [BIG_ELEMS];
__device__ __nv_bfloat16 g_wqhi[3145728];
__device__ __nv_bfloat16 g_wqlo[3145728];
__device__ __nv_bfloat16 g_wohi[1048576];
__device__ __nv_bfloat16 g_wolo[1048576];
__device__ __nv_bfloat16 g_ohi [BIG_ELEMS];
__device__ __nv_bfloat16 g_olo [BIG_ELEMS];

// ===========================================================================
// helpers (all portable PTX: sm_80+ features only — no arch-suffix ops)
// ===========================================================================
static __device__ __forceinline__ uint32_t smem_u32(const void* p) {
    uint32_t a;
    asm("{ .reg .u64 t; cvta.to.shared.u64 t, %1; cvt.u32.u64 %0, t; }"
        : "=r"(a) : "l"(p));
    return a;
}
static __device__ __forceinline__ uint32_t sw128(uint32_t o) {
    return o ^ ((o >> 3) & 0x70);
}
static __device__ __forceinline__ void cp16(uint32_t sdst, const void* gsrc) {
    asm volatile("cp.async.cg.shared.global [%0], [%1], 16;"
                 :: "r"(sdst), "l"(__cvta_generic_to_global(gsrc)) : "memory");
}
static __device__ __forceinline__ void cp_commit() {
    asm volatile("cp.async.commit_group;" ::: "memory");
}
static __device__ __forceinline__ void cp_wait1() {
    asm volatile("cp.async.wait_group 1;" ::: "memory");
}
static __device__ __forceinline__ void ldsm_x4(uint32_t* r, uint32_t addr) {
    asm volatile("ldmatrix.sync.aligned.m8n8.x4.shared.b16 {%0,%1,%2,%3}, [%4];"
                 : "=r"(r[0]), "=r"(r[1]), "=r"(r[2]), "=r"(r[3]) : "r"(addr));
}
static __device__ __forceinline__ void mma_bf16(float* d, const uint32_t* a, const uint32_t* b) {
    asm volatile(
        "mma.sync.aligned.m16n8k16.row.col.f32.bf16.bf16.f32 "
        "{%0,%1,%2,%3}, {%4,%5,%6,%7}, {%8,%9}, {%0,%1,%2,%3};"
        : "+f"(d[0]), "+f"(d[1]), "+f"(d[2]), "+f"(d[3])
        : "r"(a[0]), "r"(a[1]), "r"(a[2]), "r"(a[3]), "r"(b[0]), "r"(b[1]));
}
// fp32 float4 -> (hi, lo) bf16 pairs packed as 2x uint2
static __device__ __forceinline__ void cvt4(const float4 x, uint2& hv, uint2& lv) {
    __nv_bfloat16 h0 = __float2bfloat16_rn(x.x);
    __nv_bfloat16 h1 = __float2bfloat16_rn(x.y);
    __nv_bfloat16 h2 = __float2bfloat16_rn(x.z);
    __nv_bfloat16 h3 = __float2bfloat16_rn(x.w);
    __nv_bfloat162 hp0 = __halves2bfloat162(h0, h1);
    __nv_bfloat162 hp1 = __halves2bfloat162(h2, h3);
    __nv_bfloat162 lp0 = __floats2bfloat162_rn(x.x - __bfloat162float(h0),
                                               x.y - __bfloat162float(h1));
    __nv_bfloat162 lp1 = __floats2bfloat162_rn(x.z - __bfloat162float(h2),
                                               x.w - __bfloat162float(h3));
    hv.x = *reinterpret_cast<uint32_t*>(&hp0);
    hv.y = *reinterpret_cast<uint32_t*>(&hp1);
    lv.x = *reinterpret_cast<uint32_t*>(&lp0);
    lv.y = *reinterpret_cast<uint32_t*>(&lp1);
}

// ===========================================================================
// K0: split fp32 -> (hi, lo) bf16.  which: 0=x, 1=w_qkv, 2=w_out, 3=g_o
// ===========================================================================
__global__ void split_kernel(const float4* __restrict__ src, int n4, int which)
{
    __nv_bfloat16 *hi, *lo;
    const float4* s = src;
    if      (which == 0) { hi = g_xhi;  lo = g_xlo;  }
    else if (which == 1) { hi = g_wqhi; lo = g_wqlo; }
    else if (which == 2) { hi = g_wohi; lo = g_wolo; }
    else                 { hi = g_ohi;  lo = g_olo;  s = reinterpret_cast<const float4*>(g_o); }
    uint2* h2 = reinterpret_cast<uint2*>(hi);
    uint2* l2 = reinterpret_cast<uint2*>(lo);
    for (int i = blockIdx.x * blockDim.x + threadIdx.x; i < n4; i += gridDim.x * blockDim.x) {
        uint2 hv, lv;
        cvt4(s[i], hv, lv);
        h2[i] = hv;
        l2[i] = lv;
    }
}

// ===========================================================================
// K1/K6: bf16x3 tensor-core GEMM via mma.sync (HMMA path; tcgen05 is not
// assemblable on this harness's plain compute_103 target).
// C[16384, N] = A[16384,1024] @ W[N,1024]^T, fp32 accum,
// C ~= Ahi*Bhi + Ahi*Blo + Alo*Bhi  (lo*lo dropped, ~2^-18 relative)
// Tile 128x128, KC=64, cp.async double-buffered, SW128-swizzled smem.
// MODE 0: QKV (N=3072), epilogue scatters into bucketed q/k/v
// MODE 1: OUT (N=1024), A gathered from bucketed g_ohi/g_olo, +bias
// ===========================================================================
#define SA_HI 0
#define SA_LO 16384
#define SB_HI 32768
#define SB_LO 49152
#define GBUF  65536
#define GEMM_SMEM_BYTES 131072

template<int MODE>
__global__ void __launch_bounds__(256)
mma_gemm_kernel(const float* __restrict__ bias, float* __restrict__ out)
{
    extern __shared__ char smx[];
    const uint32_t sbase = smem_u32(smx);
    const int tid  = threadIdx.x;
    const int wid  = tid >> 5, lane = tid & 31;
    const int m0   = blockIdx.x * 128;
    const int n0   = blockIdx.y * 128;
    const int wm   = (wid >> 2) * 64;
    const int wn   = (wid & 3) * 32;

    const __nv_bfloat16* Bh = (MODE == 0) ? g_wqhi : g_wohi;
    const __nv_bfloat16* Bl = (MODE == 0) ? g_wqlo : g_wolo;

    // ---- async tile loader: A/B (hi+lo) 128x64 bf16 each, swizzled --------
    auto load_chunk = [&](int c, int buf) {
        const int k0 = c * 64;
        const uint32_t sb = sbase + buf * GBUF;
        #pragma unroll
        for (int i = 0; i < 4; i++) {
            int idx = tid + i * 256;            // 0..1023
            int row = idx >> 3, c8 = idx & 7;   // row 0..127, 16B chunk 0..7
            uint32_t soff = sw128((uint32_t)(row * 128 + c8 * 16));
            // A
            size_t ga;
            if (MODE == 0) {
                ga = (size_t)(m0 + row) * 1024 + k0 + c8 * 8;
            } else {
                int k  = k0 + c8 * 8;
                int hh = k >> 7, dh = k & 127;
                int m  = m0 + row;
                int b2 = m >> 12, t = m & 4095;
                ga = (((size_t)((b2 * 8 + hh) * 64 + (t >> 6)) * 64) + (t & 63)) * 128 + dh;
            }
            const __nv_bfloat16* ah = (MODE == 0) ? g_xhi : g_ohi;
            const __nv_bfloat16* al = (MODE == 0) ? g_xlo : g_olo;
            cp16(sb + SA_HI + soff, ah + ga);
            cp16(sb + SA_LO + soff, al + ga);
            // B
            size_t gb = (size_t)(n0 + row) * 1024 + k0 + c8 * 8;
            cp16(sb + SB_HI + soff, Bh + gb);
            cp16(sb + SB_LO + soff, Bl + gb);
        }
    };

    float acc[4][4][4] = {};

    load_chunk(0, 0);
    cp_commit();

    for (int c = 0; c < 16; c++) {
        if (c + 1 < 16) load_chunk(c + 1, (c + 1) & 1);
        cp_commit();
        cp_wait1();
        __syncthreads();

        const uint32_t sb = sbase + (c & 1) * GBUF;
        #pragma unroll
        for (int ks = 0; ks < 4; ks++) {
            uint32_t ah[4][4], al[4][4];
            #pragma unroll
            for (int mt = 0; mt < 4; mt++) {
                uint32_t off = sw128((uint32_t)((wm + mt * 16 + (lane & 15)) * 128
                                                + ks * 32 + (lane >> 4) * 16));
                ldsm_x4(ah[mt], sb + SA_HI + off);
                ldsm_x4(al[mt], sb + SA_LO + off);
            }
            uint32_t bh[2][4], bl[2][4];
            #pragma unroll
            for (int p = 0; p < 2; p++) {
                uint32_t off = sw128((uint32_t)((wn + p * 16 + ((lane >> 4) << 3) + (lane & 7)) * 128
                                                + ks * 32 + (((lane >> 3) & 1) << 4)));
                ldsm_x4(bh[p], sb + SB_HI + off);
                ldsm_x4(bl[p], sb + SB_LO + off);
            }
            #pragma unroll
            for (int mt = 0; mt < 4; mt++)
                #pragma unroll
                for (int nt = 0; nt < 4; nt++) {
                    const uint32_t* bhp = &bh[nt >> 1][(nt & 1) * 2];
                    const uint32_t* blp = &bl[nt >> 1][(nt & 1) * 2];
                    mma_bf16(acc[mt][nt], ah[mt], bhp);
                    mma_bf16(acc[mt][nt], ah[mt], blp);
                    mma_bf16(acc[mt][nt], al[mt], bhp);
                }
        }
        __syncthreads();
    }

    // ---- epilogue: fragment layout (g=lane>>2, t2=(lane&3)*2) -------------
    const int g  = lane >> 2;
    const int t2 = (lane & 3) * 2;
    #pragma unroll
    for (int mt = 0; mt < 4; mt++)
        #pragma unroll
        for (int nt = 0; nt < 4; nt++) {
            int col = n0 + wn + nt * 8 + t2;
            #pragma unroll
            for (int half = 0; half < 2; half++) {
                int row = m0 + wm + mt * 16 + g + half * 8;
                float v0 = acc[mt][nt][half * 2 + 0];
                float v1 = acc[mt][nt][half * 2 + 1];
                if (MODE == 0) {
                    int which = col >> 10;
                    float* dst = (which == 0) ? g_q : (which == 1) ? g_k : g_v;
                    int h  = (col >> 7) & 7, dh = col & 127;
                    int b2 = row >> 12, t = row & 4095;
                    size_t o = (((size_t)((b2 * 8 + h) * 64 + (t >> 6)) * 64) + (t & 63)) * 128 + dh;
                    *reinterpret_cast<float2*>(&dst[o]) = make_float2(v0, v1);
                } else {
                    *reinterpret_cast<float2*>(&out[(size_t)row * 1024 + col]) =
                        make_float2(v0 + bias[col], v1 + bias[col + 1]);
                }
            }
        }
}

// ===========================================================================
// K2: bucket key summaries  bkr[bh,u,dh] = sum_p k[bh,u,p,dh]
// ===========================================================================
__global__ void bucket_sum_kernel()
{
    const int bu = blockIdx.x;
    const int dh = threadIdx.x;
    const float* src = &g_k[(size_t)bu * TILE_ELEMS];
    float s = 0.f;
    #pragma unroll
    for (int p = 0; p < 64; p++) s += src[p * 128 + dh];
    g_bkr[bu * 128 + dh] = s;
}

// ===========================================================================
// K3: sorting logits + gumbel + 5 sinkhorn iterations + tril(exp(.),-1)
// ===========================================================================
__global__ void __launch_bounds__(256)
sinkhorn_kernel(const float* __restrict__ sort_w, const float* __restrict__ noise_u)
{
    __shared__ float R[64][65];
    const int bh  = blockIdx.x;
    const int h   = bh & 7;
    const int tid = threadIdx.x;

    for (int i = tid; i < 4096; i += 256) {
        int u = i >> 6, v = i & 63;
        const float* br = &g_bkr[bh * 8192 + u * 128];
        const float* ew = &sort_w[h * 8192];
        float s = 0.f;
        #pragma unroll 8
        for (int d = 0; d < 128; d++) s += br[d] * ew[d * 64 + v];
        float r  = logf(fmaxf(s, 0.f) + 1e-6f);
        float nu = noise_u[bh * 4096 + i];
        float gb = -logf(-logf(nu + 1e-4f) + 1e-4f);
        R[u][v] = (r + gb) * (1.0f / 0.75f);
    }
    __syncthreads();

    const int warp = tid >> 5, lane = tid & 31;
    for (int it = 0; it < 5; it++) {
        for (int r = warp; r < 64; r += 8) {
            float x0 = R[r][lane], x1 = R[r][lane + 32];
            float m = fmaxf(x0, x1);
            #pragma unroll
            for (int o = 16; o; o >>= 1) m = fmaxf(m, __shfl_xor_sync(0xffffffffu, m, o));
            float s = expf(x0 - m) + expf(x1 - m);
            #pragma unroll
            for (int o = 16; o; o >>= 1) s += __shfl_xor_sync(0xffffffffu, s, o);
            float l = m + logf(s);
            R[r][lane]      = x0 - l;
            R[r][lane + 32] = x1 - l;
        }
        __syncthreads();
        if (tid < 64) {
            float m = -INFINITY;
            for (int u2 = 0; u2 < 64; u2++) m = fmaxf(m, R[u2][tid]);
            float s = 0.f;
            for (int u2 = 0; u2 < 64; u2++) s += expf(R[u2][tid] - m);
            float l = m + logf(s);
            for (int u2 = 0; u2 < 64; u2++) R[u2][tid] -= l;
        }
        __syncthreads();
    }
    for (int i = tid; i < 4096; i += 256) {
        int u = i >> 6, v = i & 63;
        g_R[bh * 4096 + i] = (u > v) ? expf(R[u][v]) : 0.f;
    }
}

// ===========================================================================
// K4: soft permute  kre[bh,u] = sum_{v<u} R[u,v]*k[bh,v]  (same for v)
// ===========================================================================
__global__ void __launch_bounds__(256, 2)
permute_kernel()
{
    __shared__ float Rs[64];
    const int blk = blockIdx.x;
    const int bh  = blk >> 6, u = blk & 63;
    const int tid = threadIdx.x;
    if (tid < 64) Rs[tid] = g_R[bh * 4096 + u * 64 + tid];
    __syncthreads();

    float ak[32] = {}, av[32] = {};
    const int dh = tid & 127;
    const int hi = tid >> 7;
    const size_t bhbase = (size_t)bh * 64 * TILE_ELEMS;
    for (int v = 0; v < u; v++) {
        float r = Rs[v];
        const float* kp = &g_k[bhbase + (size_t)v * TILE_ELEMS];
        const float* vp = &g_v[bhbase + (size_t)v * TILE_ELEMS];
        #pragma unroll
        for (int i = 0; i < 32; i++) {
            int off = (2 * i + hi) * 128 + dh;
            ak[i] = fmaf(r, kp[off], ak[i]);
            av[i] = fmaf(r, vp[off], av[i]);
        }
    }
    const size_t obase = (size_t)blk * TILE_ELEMS;
    #pragma unroll
    for (int i = 0; i < 32; i++) {
        int off = (2 * i + hi) * 128 + dh;
        g_kre[obase + off] = ak[i];
        g_vre[obase + off] = av[i];
    }
}

// ===========================================================================
// K5: bucketed attention, one CTA per (bh,u)
// ===========================================================================
#define ATTN_SMEM_FLOATS (8192 + 128 * 132 + 64 * 132)
#define ATTN_SMEM_BYTES  (ATTN_SMEM_FLOATS * 4)

__global__ void __launch_bounds__(256)
attn_kernel()
{
    extern __shared__ float sm[];
    float* qs = sm;
    float* kt = sm + 8192;
    float* ds = sm + 8192 + 128 * 132;

    const int blk = blockIdx.x;
    const int tid = threadIdx.x;
    const size_t base = (size_t)blk * TILE_ELEMS;

    for (int i = tid; i < 8192; i += 256) qs[i] = g_q[base + i];
    for (int i = tid; i < 8192; i += 256) {
        int j = i >> 7, d = i & 127;
        kt[d * 132 + j] = g_kre[base + i];
    }
    for (int i = tid; i < 8192; i += 256) {
        int j = i >> 7, d = i & 127;
        kt[d * 132 + 64 + j] = g_k[base + i];
    }
    __syncthreads();

    const int tx = tid & 15, ty = tid >> 4;
    const int r0 = ty * 4, c0 = tx * 8;

    float acc[4][8] = {};
    for (int d = 0; d < 128; d++) {
        float a[4];
        #pragma unroll
        for (int i = 0; i < 4; i++) a[i] = qs[(r0 + i) * 128 + d];
        float4 b0 = *(float4*)&kt[d * 132 + c0];
        float4 b1 = *(float4*)&kt[d * 132 + c0 + 4];
        float b[8] = {b0.x, b0.y, b0.z, b0.w, b1.x, b1.y, b1.z, b1.w};
        #pragma unroll
        for (int i = 0; i < 4; i++)
            #pragma unroll
            for (int j = 0; j < 8; j++)
                acc[i][j] = fmaf(a[i], b[j], acc[i][j]);
    }
    #pragma unroll
    for (int i = 0; i < 4; i++)
        #pragma unroll
        for (int j = 0; j < 8; j++)
            ds[(r0 + i) * 132 + c0 + j] = acc[i][j] * 0.03125f;
    __syncthreads();

    for (int i = tid; i < 8192; i += 256) {
        int j = i >> 7, e = i & 127;
        kt[j * 132 + e] = g_vre[base + i];
    }
    for (int i = tid; i < 8192; i += 256) {
        int j = i >> 7, e = i & 127;
        kt[(j + 64) * 132 + e] = g_v[base + i];
    }
    if (tid < 64) {
        float m = -INFINITY;
        for (int j = 0; j < 128; j++) m = fmaxf(m, ds[tid * 132 + j]);
        float s = 0.f;
        for (int j = 0; j < 128; j++) {
            float e = expf(ds[tid * 132 + j] - m);
            ds[tid * 132 + j] = e;
            s += e;
        }
        float inv = 1.f / s;
        for (int j = 0; j < 128; j++) ds[tid * 132 + j] *= inv;
    }
    __syncthreads();

    float o[4][8] = {};
    for (int j = 0; j < 128; j++) {
        float a[4];
        #pragma unroll
        for (int i = 0; i < 4; i++) a[i] = ds[(r0 + i) * 132 + j];
        float4 b0 = *(float4*)&kt[j * 132 + c0];
        float4 b1 = *(float4*)&kt[j * 132 + c0 + 4];
        float b[8] = {b0.x, b0.y, b0.z, b0.w, b1.x, b1.y, b1.z, b1.w};
        #pragma unroll
        for (int i = 0; i < 4; i++)
            #pragma unroll
            for (int jj = 0; jj < 8; jj++)
                o[i][jj] = fmaf(a[i], b[jj], o[i][jj]);
    }
    #pragma unroll
    for (int i = 0; i < 4; i++) {
        *(float4*)&g_o[base + (r0 + i) * 128 + c0]     = make_float4(o[i][0], o[i][1], o[i][2], o[i][3]);
        *(float4*)&g_o[base + (r0 + i) * 128 + c0 + 4] = make_float4(o[i][4], o[i][5], o[i][6], o[i][7]);
    }
}

// ===========================================================================
extern "C" void kernel_launch(void* const* d_in, const int* in_sizes, int n_in,
                              void* d_out, int out_size)
{
    (void)in_sizes; (void)n_in; (void)out_size;
    const float* x      = (const float*)d_in[0];
    const float* w_qkv  = (const float*)d_in[1];
    const float* sort_w = (const float*)d_in[2];
    const float* w_out  = (const float*)d_in[3];
    const float* b_out  = (const float*)d_in[4];
    const float* noise  = (const float*)d_in[5];
    float* out = (float*)d_out;

    cudaFuncSetAttribute(attn_kernel, cudaFuncAttributeMaxDynamicSharedMemorySize,
                         ATTN_SMEM_BYTES);
    cudaFuncSetAttribute(mma_gemm_kernel<0>, cudaFuncAttributeMaxDynamicSharedMemorySize,
                         GEMM_SMEM_BYTES);
    cudaFuncSetAttribute(mma_gemm_kernel<1>, cudaFuncAttributeMaxDynamicSharedMemorySize,
                         GEMM_SMEM_BYTES);

    split_kernel<<<4096, 256>>>((const float4*)x,     4194304, 0);
    split_kernel<<<3072, 256>>>((const float4*)w_qkv,  786432, 1);
    split_kernel<<<1024, 256>>>((const float4*)w_out,  262144, 2);

    mma_gemm_kernel<0><<<dim3(128, 24), 256, GEMM_SMEM_BYTES>>>(nullptr, nullptr);

    bucket_sum_kernel<<<2048, 128>>>();
    sinkhorn_kernel<<<32, 256>>>(sort_w, noise);
    permute_kernel<<<2048, 256>>>();
    attn_kernel<<<2048, 256, ATTN_SMEM_BYTES>>>();

    split_kernel<<<4096, 256>>>(nullptr, 4194304, 3);
    mma_gemm_kernel<1><<<dim3(128, 8), 256, GEMM_SMEM_BYTES>>>(b_out, out);
}

// round 7
// speedup vs baseline: 2.1955x; 1.0296x over previous
#include <cuda_runtime.h>
#include <cuda_bf16.h>
#include <math.h>
#include <stdint.h>

// Problem constants: B=4, T=4096, D=1024, H=8, BUCKETS=64, BSZ=64, DH=128
#define TILE_ELEMS    8192          // BSZ * DH
#define BIG_ELEMS     16777216      // 2048 * 8192

// -------- device scratch (static globals: allocation-free, graph-safe) -----
__device__ float g_q  [BIG_ELEMS];
__device__ float g_k  [BIG_ELEMS];
__device__ float g_v  [BIG_ELEMS];
__device__ float g_kre[BIG_ELEMS];
__device__ float g_vre[BIG_ELEMS];
__device__ float g_bkr[32 * 64 * 128];
__device__ float g_R  [32 * 64 * 64];

// bf16 hi/lo split operands for tensor-core GEMMs
__device__ __nv_bfloat16 g_xhi [BIG_ELEMS];
__device__ __nv_bfloat16 g_xlo [BIG_ELEMS];
__device__ __nv_bfloat16 g_wqhi[3145728];
__device__ __nv_bfloat16 g_wqlo[3145728];
__device__ __nv_bfloat16 g_wohi[1048576];
__device__ __nv_bfloat16 g_wolo[1048576];
__device__ __nv_bfloat16 g_ohi [BIG_ELEMS];   // written directly by attn epilogue
__device__ __nv_bfloat16 g_olo [BIG_ELEMS];

// ===========================================================================
// helpers (portable PTX, sm_80-era features only)
// ===========================================================================
static __device__ __forceinline__ uint32_t smem_u32(const void* p) {
    uint32_t a;
    asm("{ .reg .u64 t; cvta.to.shared.u64 t, %1; cvt.u32.u64 %0, t; }"
        : "=r"(a) : "l"(p));
    return a;
}
static __device__ __forceinline__ uint32_t sw128(uint32_t o) {
    return o ^ ((o >> 3) & 0x70);
}
static __device__ __forceinline__ uint32_t swzK(uint32_t o) {   // 512B-pitch rows
    return o ^ ((o >> 5) & 0x70);
}
static __device__ __forceinline__ void cp16(uint32_t sdst, const void* gsrc) {
    asm volatile("cp.async.cg.shared.global [%0], [%1], 16;"
                 :: "r"(sdst), "l"(__cvta_generic_to_global(gsrc)) : "memory");
}
static __device__ __forceinline__ void cp_commit() {
    asm volatile("cp.async.commit_group;" ::: "memory");
}
static __device__ __forceinline__ void cp_wait2() {
    asm volatile("cp.async.wait_group 2;" ::: "memory");
}
static __device__ __forceinline__ void ldsm_x4(uint32_t* r, uint32_t addr) {
    asm volatile("ldmatrix.sync.aligned.m8n8.x4.shared.b16 {%0,%1,%2,%3}, [%4];"
                 : "=r"(r[0]), "=r"(r[1]), "=r"(r[2]), "=r"(r[3]) : "r"(addr));
}
static __device__ __forceinline__ void ldsm_x4_t(uint32_t* r, uint32_t addr) {
    asm volatile("ldmatrix.sync.aligned.m8n8.x4.trans.shared.b16 {%0,%1,%2,%3}, [%4];"
                 : "=r"(r[0]), "=r"(r[1]), "=r"(r[2]), "=r"(r[3]) : "r"(addr));
}
static __device__ __forceinline__ void mma_bf16(float* d, const uint32_t* a, const uint32_t* b) {
    asm volatile(
        "mma.sync.aligned.m16n8k16.row.col.f32.bf16.bf16.f32 "
        "{%0,%1,%2,%3}, {%4,%5,%6,%7}, {%8,%9}, {%0,%1,%2,%3};"
        : "+f"(d[0]), "+f"(d[1]), "+f"(d[2]), "+f"(d[3])
        : "r"(a[0]), "r"(a[1]), "r"(a[2]), "r"(a[3]), "r"(b[0]), "r"(b[1]));
}
// fp32 float4 -> (hi, lo) bf16 pairs packed as 2x uint2
static __device__ __forceinline__ void cvt4(const float4 x, uint2& hv, uint2& lv) {
    __nv_bfloat16 h0 = __float2bfloat16_rn(x.x);
    __nv_bfloat16 h1 = __float2bfloat16_rn(x.y);
    __nv_bfloat16 h2 = __float2bfloat16_rn(x.z);
    __nv_bfloat16 h3 = __float2bfloat16_rn(x.w);
    __nv_bfloat162 hp0 = __halves2bfloat162(h0, h1);
    __nv_bfloat162 hp1 = __halves2bfloat162(h2, h3);
    __nv_bfloat162 lp0 = __floats2bfloat162_rn(x.x - __bfloat162float(h0),
                                               x.y - __bfloat162float(h1));
    __nv_bfloat162 lp1 = __floats2bfloat162_rn(x.z - __bfloat162float(h2),
                                               x.w - __bfloat162float(h3));
    hv.x = *reinterpret_cast<uint32_t*>(&hp0);
    hv.y = *reinterpret_cast<uint32_t*>(&hp1);
    lv.x = *reinterpret_cast<uint32_t*>(&lp0);
    lv.y = *reinterpret_cast<uint32_t*>(&lp1);
}

// ===========================================================================
// K0: split fp32 -> (hi, lo) bf16.  which: 0=x, 1=w_qkv, 2=w_out
// ===========================================================================
__global__ void split_kernel(const float4* __restrict__ src, int n4, int which)
{
    __nv_bfloat16 *hi, *lo;
    if      (which == 0) { hi = g_xhi;  lo = g_xlo;  }
    else if (which == 1) { hi = g_wqhi; lo = g_wqlo; }
    else                 { hi = g_wohi; lo = g_wolo; }
    uint2* h2 = reinterpret_cast<uint2*>(hi);
    uint2* l2 = reinterpret_cast<uint2*>(lo);
    for (int i = blockIdx.x * blockDim.x + threadIdx.x; i < n4; i += gridDim.x * blockDim.x) {
        uint2 hv, lv;
        cvt4(src[i], hv, lv);
        h2[i] = hv;
        l2[i] = lv;
    }
}

// ===========================================================================
// K1/K6: bf16x3 HMMA GEMM, tile 128x128, KC=32, 4-stage cp.async pipeline.
// Row-pack: 2 m-rows per 128B smem line -> sw128 conflict-free at 64B rows.
// MODE 0: QKV (N=3072) epilogue scatters bucketed q/k/v
// MODE 1: OUT (N=1024), A gathered from bucketed g_ohi/g_olo, +bias
// ===========================================================================
#define ST_A_HI 0
#define ST_A_LO 8192
#define ST_B_HI 16384
#define ST_B_LO 24576
#define STAGE_BYTES 32768
#define GEMM_SMEM_BYTES 131072     // 4 stages

template<int MODE>
__global__ void __launch_bounds__(256)
mma_gemm_kernel(const float* __restrict__ bias, float* __restrict__ out)
{
    extern __shared__ char smx[];
    const uint32_t sbase = smem_u32(smx);
    const int tid  = threadIdx.x;
    const int wid  = tid >> 5, lane = tid & 31;
    const int m0   = blockIdx.x * 128;
    const int n0   = blockIdx.y * 128;
    const int wm   = (wid >> 2) * 64;
    const int wn   = (wid & 3) * 32;

    const __nv_bfloat16* Ah = (MODE == 0) ? g_xhi  : g_ohi;
    const __nv_bfloat16* Al = (MODE == 0) ? g_xlo  : g_olo;
    const __nv_bfloat16* Bh = (MODE == 0) ? g_wqhi : g_wohi;
    const __nv_bfloat16* Bl = (MODE == 0) ? g_wqlo : g_wolo;

    auto load_chunk = [&](int c, int slot) {
        const int k0 = c * 32;
        const uint32_t sb = sbase + slot * STAGE_BYTES;
        #pragma unroll
        for (int i = 0; i < 2; i++) {
            int idx = tid + i * 256;            // 0..511
            int row = idx >> 2, c8 = idx & 3;   // row 0..127, 16B chunk 0..3
            uint32_t soff = sw128((uint32_t)((row >> 1) * 128 + (row & 1) * 64 + c8 * 16));
            size_t ga;
            if (MODE == 0) {
                ga = (size_t)(m0 + row) * 1024 + k0 + c8 * 8;
            } else {
                int k  = k0 + c8 * 8;
                int hh = k >> 7, dh = k & 127;
                int m  = m0 + row;
                int b2 = m >> 12, t = m & 4095;
                ga = (((size_t)((b2 * 8 + hh) * 64 + (t >> 6)) * 64) + (t & 63)) * 128 + dh;
            }
            cp16(sb + ST_A_HI + soff, Ah + ga);
            cp16(sb + ST_A_LO + soff, Al + ga);
            size_t gb = (size_t)(n0 + row) * 1024 + k0 + c8 * 8;
            cp16(sb + ST_B_HI + soff, Bh + gb);
            cp16(sb + ST_B_LO + soff, Bl + gb);
        }
    };

    float acc[4][4][4] = {};

    load_chunk(0, 0); cp_commit();
    load_chunk(1, 1); cp_commit();
    load_chunk(2, 2); cp_commit();

    for (int c = 0; c < 32; c++) {
        cp_wait2();
        __syncthreads();
        const uint32_t sb = sbase + (c & 3) * STAGE_BYTES;
        #pragma unroll
        for (int ks = 0; ks < 2; ks++) {
            uint32_t ah[4][4], al[4][4];
            #pragma unroll
            for (int mt = 0; mt < 4; mt++) {
                int m = wm + mt * 16 + (lane & 15);
                uint32_t off = sw128((uint32_t)((m >> 1) * 128 + (m & 1) * 64
                                                + ks * 32 + (lane >> 4) * 16));
                ldsm_x4(ah[mt], sb + ST_A_HI + off);
                ldsm_x4(al[mt], sb + ST_A_LO + off);
            }
            uint32_t bhf[2][4], blf[2][4];
            #pragma unroll
            for (int p = 0; p < 2; p++) {
                int n = wn + p * 16 + ((lane >> 4) << 3) + (lane & 7);
                uint32_t off = sw128((uint32_t)((n >> 1) * 128 + (n & 1) * 64
                                                + ks * 32 + (((lane >> 3) & 1) << 4)));
                ldsm_x4(bhf[p], sb + ST_B_HI + off);
                ldsm_x4(blf[p], sb + ST_B_LO + off);
            }
            #pragma unroll
            for (int mt = 0; mt < 4; mt++)
                #pragma unroll
                for (int nt = 0; nt < 4; nt++) {
                    const uint32_t* bhp = &bhf[nt >> 1][(nt & 1) * 2];
                    const uint32_t* blp = &blf[nt >> 1][(nt & 1) * 2];
                    mma_bf16(acc[mt][nt], ah[mt], bhp);
                    mma_bf16(acc[mt][nt], ah[mt], blp);
                    mma_bf16(acc[mt][nt], al[mt], bhp);
                }
        }
        __syncthreads();
        if (c + 3 < 32) load_chunk(c + 3, (c + 3) & 3);
        cp_commit();
    }

    const int g  = lane >> 2;
    const int t2 = (lane & 3) * 2;
    #pragma unroll
    for (int mt = 0; mt < 4; mt++)
        #pragma unroll
        for (int nt = 0; nt < 4; nt++) {
            int col = n0 + wn + nt * 8 + t2;
            #pragma unroll
            for (int half = 0; half < 2; half++) {
                int row = m0 + wm + mt * 16 + g + half * 8;
                float v0 = acc[mt][nt][half * 2 + 0];
                float v1 = acc[mt][nt][half * 2 + 1];
                if (MODE == 0) {
                    int which = col >> 10;
                    float* dst = (which == 0) ? g_q : (which == 1) ? g_k : g_v;
                    int h  = (col >> 7) & 7, dh = col & 127;
                    int b2 = row >> 12, t = row & 4095;
                    size_t o = (((size_t)((b2 * 8 + h) * 64 + (t >> 6)) * 64) + (t & 63)) * 128 + dh;
                    *reinterpret_cast<float2*>(&dst[o]) = make_float2(v0, v1);
                } else {
                    *reinterpret_cast<float2*>(&out[(size_t)row * 1024 + col]) =
                        make_float2(v0 + bias[col], v1 + bias[col + 1]);
                }
            }
        }
}

// ===========================================================================
// K2: bucket key summaries
// ===========================================================================
__global__ void bucket_sum_kernel()
{
    const int bu = blockIdx.x;
    const int dh = threadIdx.x;
    const float* src = &g_k[(size_t)bu * TILE_ELEMS];
    float s = 0.f;
    #pragma unroll
    for (int p = 0; p < 64; p++) s += src[p * 128 + dh];
    g_bkr[bu * 128 + dh] = s;
}

// ===========================================================================
// K3: sorting logits + gumbel + 5 sinkhorn iterations + tril(exp(.),-1)
// ===========================================================================
__global__ void __launch_bounds__(256)
sinkhorn_kernel(const float* __restrict__ sort_w, const float* __restrict__ noise_u)
{
    __shared__ float R[64][65];
    const int bh  = blockIdx.x;
    const int h   = bh & 7;
    const int tid = threadIdx.x;

    for (int i = tid; i < 4096; i += 256) {
        int u = i >> 6, v = i & 63;
        const float* br = &g_bkr[bh * 8192 + u * 128];
        const float* ew = &sort_w[h * 8192];
        float s = 0.f;
        #pragma unroll 8
        for (int d = 0; d < 128; d++) s += br[d] * ew[d * 64 + v];
        float r  = logf(fmaxf(s, 0.f) + 1e-6f);
        float nu = noise_u[bh * 4096 + i];
        float gb = -logf(-logf(nu + 1e-4f) + 1e-4f);
        R[u][v] = (r + gb) * (1.0f / 0.75f);
    }
    __syncthreads();

    const int warp = tid >> 5, lane = tid & 31;
    for (int it = 0; it < 5; it++) {
        for (int r = warp; r < 64; r += 8) {
            float x0 = R[r][lane], x1 = R[r][lane + 32];
            float m = fmaxf(x0, x1);
            #pragma unroll
            for (int o = 16; o; o >>= 1) m = fmaxf(m, __shfl_xor_sync(0xffffffffu, m, o));
            float s = expf(x0 - m) + expf(x1 - m);
            #pragma unroll
            for (int o = 16; o; o >>= 1) s += __shfl_xor_sync(0xffffffffu, s, o);
            float l = m + logf(s);
            R[r][lane]      = x0 - l;
            R[r][lane + 32] = x1 - l;
        }
        __syncthreads();
        if (tid < 64) {
            float m = -INFINITY;
            for (int u2 = 0; u2 < 64; u2++) m = fmaxf(m, R[u2][tid]);
            float s = 0.f;
            for (int u2 = 0; u2 < 64; u2++) s += expf(R[u2][tid] - m);
            float l = m + logf(s);
            for (int u2 = 0; u2 < 64; u2++) R[u2][tid] -= l;
        }
        __syncthreads();
    }
    for (int i = tid; i < 4096; i += 256) {
        int u = i >> 6, v = i & 63;
        g_R[bh * 4096 + i] = (u > v) ? expf(R[u][v]) : 0.f;
    }
}

// ===========================================================================
// K4: soft permute as tensor-core GEMM: kre[bh] = R[bh](64x64) @ k[bh](64x8192)
// Each CTA: one bh + one 256-column slice; k/v tiles read exactly ONCE.
// R: bf16x3 in sw128 smem (128B rows). K/V: bf16x3, 512B-pitch rows, swzK
// swizzle, B-fragments via ldmatrix.x4.trans. Output staged in smem for
// coalesced fp32 writes.
// ===========================================================================
#define PSM_RHI  0
#define PSM_RLO  8192
#define PSM_K    16384              // 64KB: Khi 32KB | Klo 32KB (reused as fp32 stage)
#define PERM_SMEM_BYTES (16384 + 65536)

__global__ void __launch_bounds__(256)
permute_kernel()
{
    extern __shared__ char psm[];
    const uint32_t sbase = smem_u32(psm);
    const int tid  = threadIdx.x;
    const int wid  = tid >> 5, lane = tid & 31;
    const int bh   = blockIdx.x >> 5;
    const int col0 = (blockIdx.x & 31) * 256;
    const int mt   = wid & 3;         // m16 block of the 64 u-rows
    const int nh   = wid >> 2;        // 128-col half of the 256-col slice
    const size_t bhbase = (size_t)bh * 524288;   // 64 * 8192

    // ---- load R[bh] -> bf16 hi/lo, sw128 (128B rows) ----------------------
    for (int i = tid; i < 1024; i += 256) {       // 4096 floats / 4
        int row = i >> 4, c4 = i & 15;
        float4 x = *reinterpret_cast<const float4*>(&g_R[bh * 4096 + row * 64 + c4 * 4]);
        uint2 hv, lv; cvt4(x, hv, lv);
        uint32_t off = sw128((uint32_t)(row * 128 + c4 * 8));
        *reinterpret_cast<uint2*>(psm + PSM_RHI + off) = hv;
        *reinterpret_cast<uint2*>(psm + PSM_RLO + off) = lv;
    }

    const float* srcs[2] = {g_k, g_v};
    float*       dsts[2] = {g_kre, g_vre};

    for (int ph = 0; ph < 2; ph++) {
        const float* src = srcs[ph];
        float*       dst = dsts[ph];

        // ---- load 64x256 tile -> bf16 hi/lo, 512B-pitch rows, swzK --------
        __syncthreads();   // (phase0: also covers R; phase>=1: stage region free)
        for (int i = tid; i < 4096; i += 256) {   // 64 rows x 64 float4
            int v = i >> 6, c4 = i & 63;
            float4 x = *reinterpret_cast<const float4*>(&src[bhbase + (size_t)v * 8192 + col0 + c4 * 4]);
            uint2 hv, lv; cvt4(x, hv, lv);
            uint32_t off = swzK((uint32_t)(v * 512 + c4 * 8));
            *reinterpret_cast<uint2*>(psm + PSM_K + off)         = hv;
            *reinterpret_cast<uint2*>(psm + PSM_K + 32768 + off) = lv;
        }
        __syncthreads();

        // ---- mma: out[u][col] = sum_v R[u][v] * K[v][col], bf16x3 ---------
        float acc[16][4];
        #pragma unroll
        for (int f = 0; f < 16; f++)
            #pragma unroll
            for (int e = 0; e < 4; e++) acc[f][e] = 0.f;

        #pragma unroll
        for (int ks = 0; ks < 4; ks++) {          // v0 = ks*16
            uint32_t ahf[4], alf[4];
            {
                int u = mt * 16 + (lane & 15);
                uint32_t off = sw128((uint32_t)(u * 128 + ks * 32 + (lane >> 4) * 16));
                ldsm_x4(ahf, sbase + PSM_RHI + off);
                ldsm_x4(alf, sbase + PSM_RLO + off);
            }
            #pragma unroll
            for (int j2 = 0; j2 < 8; j2++) {      // n16 blocks within 128 cols
                int n0 = nh * 128 + j2 * 16;
                uint32_t off = swzK((uint32_t)((ks * 16 + (lane & 15)) * 512
                                               + (n0 + (lane >> 4) * 8) * 2));
                uint32_t khf[4], klf[4];
                ldsm_x4_t(khf, sbase + PSM_K + off);
                ldsm_x4_t(klf, sbase + PSM_K + 32768 + off);
                #pragma unroll
                for (int nb = 0; nb < 2; nb++) {
                    float* a = acc[j2 * 2 + nb];
                    mma_bf16(a, ahf, &khf[nb * 2]);
                    mma_bf16(a, ahf, &klf[nb * 2]);
                    mma_bf16(a, alf, &khf[nb * 2]);
                }
            }
        }
        __syncthreads();   // all ldsm done before stage overwrites K region

        // ---- stage fp32 [64][256] in smem, then coalesced gmem writes -----
        float* stage = reinterpret_cast<float*>(psm + PSM_K);
        const int g2 = lane >> 2, t2 = (lane & 3) * 2;
        #pragma unroll
        for (int j2 = 0; j2 < 8; j2++)
            #pragma unroll
            for (int nb = 0; nb < 2; nb++) {
                int col = nh * 128 + j2 * 16 + nb * 8 + t2;
                #pragma unroll
                for (int half = 0; half < 2; half++) {
                    int u = mt * 16 + g2 + half * 8;
                    *reinterpret_cast<float2*>(&stage[u * 256 + col]) =
                        make_float2(acc[j2 * 2 + nb][half * 2 + 0],
                                    acc[j2 * 2 + nb][half * 2 + 1]);
                }
            }
        __syncthreads();
        for (int i = tid; i < 4096; i += 256) {
            int u = i >> 6, c4 = i & 63;
            *reinterpret_cast<float4*>(&dst[bhbase + (size_t)u * 8192 + col0 + c4 * 4]) =
                *reinterpret_cast<const float4*>(&stage[u * 256 + c4 * 4]);
        }
    }
}

// ===========================================================================
// K5: bucketed attention, one CTA per (bh,u); epilogue writes bf16 hi/lo
// directly for the output GEMM (no fp32 g_o round-trip).
// ===========================================================================
#define ATTN_SMEM_FLOATS (8192 + 128 * 132 + 64 * 132)
#define ATTN_SMEM_BYTES  (ATTN_SMEM_FLOATS * 4)

__global__ void __launch_bounds__(256)
attn_kernel()
{
    extern __shared__ float sm[];
    float* qs = sm;
    float* kt = sm + 8192;
    float* ds = sm + 8192 + 128 * 132;

    const int blk = blockIdx.x;
    const int tid = threadIdx.x;
    const size_t base = (size_t)blk * TILE_ELEMS;

    for (int i = tid; i < 8192; i += 256) qs[i] = g_q[base + i];
    for (int i = tid; i < 8192; i += 256) {
        int j = i >> 7, d = i & 127;
        kt[d * 132 + j] = g_kre[base + i];
    }
    for (int i = tid; i < 8192; i += 256) {
        int j = i >> 7, d = i & 127;
        kt[d * 132 + 64 + j] = g_k[base + i];
    }
    __syncthreads();

    const int tx = tid & 15, ty = tid >> 4;
    const int r0 = ty * 4, c0 = tx * 8;

    float acc[4][8] = {};
    for (int d = 0; d < 128; d++) {
        float a[4];
        #pragma unroll
        for (int i = 0; i < 4; i++) a[i] = qs[(r0 + i) * 128 + d];
        float4 b0 = *(float4*)&kt[d * 132 + c0];
        float4 b1 = *(float4*)&kt[d * 132 + c0 + 4];
        float b[8] = {b0.x, b0.y, b0.z, b0.w, b1.x, b1.y, b1.z, b1.w};
        #pragma unroll
        for (int i = 0; i < 4; i++)
            #pragma unroll
            for (int j = 0; j < 8; j++)
                acc[i][j] = fmaf(a[i], b[j], acc[i][j]);
    }
    #pragma unroll
    for (int i = 0; i < 4; i++)
        #pragma unroll
        for (int j = 0; j < 8; j++)
            ds[(r0 + i) * 132 + c0 + j] = acc[i][j] * 0.03125f;
    __syncthreads();

    for (int i = tid; i < 8192; i += 256) {
        int j = i >> 7, e = i & 127;
        kt[j * 132 + e] = g_vre[base + i];
    }
    for (int i = tid; i < 8192; i += 256) {
        int j = i >> 7, e = i & 127;
        kt[(j + 64) * 132 + e] = g_v[base + i];
    }
    if (tid < 64) {
        float m = -INFINITY;
        for (int j = 0; j < 128; j++) m = fmaxf(m, ds[tid * 132 + j]);
        float s = 0.f;
        for (int j = 0; j < 128; j++) {
            float e = expf(ds[tid * 132 + j] - m);
            ds[tid * 132 + j] = e;
            s += e;
        }
        float inv = 1.f / s;
        for (int j = 0; j < 128; j++) ds[tid * 132 + j] *= inv;
    }
    __syncthreads();

    float o[4][8] = {};
    for (int j = 0; j < 128; j++) {
        float a[4];
        #pragma unroll
        for (int i = 0; i < 4; i++) a[i] = ds[(r0 + i) * 132 + j];
        float4 b0 = *(float4*)&kt[j * 132 + c0];
        float4 b1 = *(float4*)&kt[j * 132 + c0 + 4];
        float b[8] = {b0.x, b0.y, b0.z, b0.w, b1.x, b1.y, b1.z, b1.w};
        #pragma unroll
        for (int i = 0; i < 4; i++)
            #pragma unroll
            for (int jj = 0; jj < 8; jj++)
                o[i][jj] = fmaf(a[i], b[jj], o[i][jj]);
    }
    #pragma unroll
    for (int i = 0; i < 4; i++) {
        size_t off = base + (r0 + i) * 128 + c0;
        float4 o0 = make_float4(o[i][0], o[i][1], o[i][2], o[i][3]);
        float4 o1 = make_float4(o[i][4], o[i][5], o[i][6], o[i][7]);
        uint2 hv, lv;
        cvt4(o0, hv, lv);
        *reinterpret_cast<uint2*>(&g_ohi[off]) = hv;
        *reinterpret_cast<uint2*>(&g_olo[off]) = lv;
        cvt4(o1, hv, lv);
        *reinterpret_cast<uint2*>(&g_ohi[off + 4]) = hv;
        *reinterpret_cast<uint2*>(&g_olo[off + 4]) = lv;
    }
}

// ===========================================================================
extern "C" void kernel_launch(void* const* d_in, const int* in_sizes, int n_in,
                              void* d_out, int out_size)
{
    (void)in_sizes; (void)n_in; (void)out_size;
    const float* x      = (const float*)d_in[0];
    const float* w_qkv  = (const float*)d_in[1];
    const float* sort_w = (const float*)d_in[2];
    const float* w_out  = (const float*)d_in[3];
    const float* b_out  = (const float*)d_in[4];
    const float* noise  = (const float*)d_in[5];
    float* out = (float*)d_out;

    cudaFuncSetAttribute(attn_kernel, cudaFuncAttributeMaxDynamicSharedMemorySize,
                         ATTN_SMEM_BYTES);
    cudaFuncSetAttribute(mma_gemm_kernel<0>, cudaFuncAttributeMaxDynamicSharedMemorySize,
                         GEMM_SMEM_BYTES);
    cudaFuncSetAttribute(mma_gemm_kernel<1>, cudaFuncAttributeMaxDynamicSharedMemorySize,
                         GEMM_SMEM_BYTES);
    cudaFuncSetAttribute(permute_kernel, cudaFuncAttributeMaxDynamicSharedMemorySize,
                         PERM_SMEM_BYTES);

    split_kernel<<<4096, 256>>>((const float4*)x,     4194304, 0);
    split_kernel<<<3072, 256>>>((const float4*)w_qkv,  786432, 1);
    split_kernel<<<1024, 256>>>((const float4*)w_out,  262144, 2);

    mma_gemm_kernel<0><<<dim3(128, 24), 256, GEMM_SMEM_BYTES>>>(nullptr, nullptr);

    bucket_sum_kernel<<<2048, 128>>>();
    sinkhorn_kernel<<<32, 256>>>(sort_w, noise);
    permute_kernel<<<1024, 256, PERM_SMEM_BYTES>>>();
    attn_kernel<<<2048, 256, ATTN_SMEM_BYTES>>>();

    mma_gemm_kernel<1><<<dim3(128, 8), 256, GEMM_SMEM_BYTES>>>(b_out, out);
}

// round 9
// speedup vs baseline: 2.3716x; 1.0802x over previous
#include <cuda_runtime.h>
#include <cuda_bf16.h>
#include <math.h>
#include <stdint.h>

// Problem constants: B=4, T=4096, D=1024, H=8, BUCKETS=64, BSZ=64, DH=128
#define TILE_ELEMS    8192          // BSZ * DH
#define BIG_ELEMS     16777216      // 2048 * 8192

// -------- device scratch (static globals: allocation-free, graph-safe) -----
__device__ float g_q  [BIG_ELEMS];
__device__ float g_k  [BIG_ELEMS];
__device__ float g_v  [BIG_ELEMS];
__device__ float g_kre[BIG_ELEMS];
__device__ float g_vre[BIG_ELEMS];
__device__ float g_bkr[32 * 64 * 128];
__device__ float g_R  [32 * 64 * 64];

// bf16 hi/lo split operands for tensor-core GEMMs
__device__ __nv_bfloat16 g_xhi [BIG_ELEMS];
__device__ __nv_bfloat16 g_xlo [BIG_ELEMS];
__device__ __nv_bfloat16 g_wqhi[3145728];
__device__ __nv_bfloat16 g_wqlo[3145728];
__device__ __nv_bfloat16 g_wohi[1048576];
__device__ __nv_bfloat16 g_wolo[1048576];
__device__ __nv_bfloat16 g_ohi [BIG_ELEMS];   // written directly by attn epilogue
__device__ __nv_bfloat16 g_olo [BIG_ELEMS];

// ===========================================================================
// helpers (portable PTX, sm_80-era features only)
// ===========================================================================
static __device__ __forceinline__ uint32_t smem_u32(const void* p) {
    uint32_t a;
    asm("{ .reg .u64 t; cvta.to.shared.u64 t, %1; cvt.u32.u64 %0, t; }"
        : "=r"(a) : "l"(p));
    return a;
}
static __device__ __forceinline__ uint32_t sw128(uint32_t o) {
    return o ^ ((o >> 3) & 0x70);
}
static __device__ __forceinline__ uint32_t swzK(uint32_t o) {   // 512B-pitch rows
    return o ^ ((o >> 5) & 0x70);
}
static __device__ __forceinline__ void cp16(uint32_t sdst, const void* gsrc) {
    asm volatile("cp.async.cg.shared.global [%0], [%1], 16;"
                 :: "r"(sdst), "l"(__cvta_generic_to_global(gsrc)) : "memory");
}
static __device__ __forceinline__ void cp_commit() {
    asm volatile("cp.async.commit_group;" ::: "memory");
}
static __device__ __forceinline__ void cp_wait1() {
    asm volatile("cp.async.wait_group 1;" ::: "memory");
}
static __device__ __forceinline__ void ldsm_x4(uint32_t* r, uint32_t addr) {
    asm volatile("ldmatrix.sync.aligned.m8n8.x4.shared.b16 {%0,%1,%2,%3}, [%4];"
                 : "=r"(r[0]), "=r"(r[1]), "=r"(r[2]), "=r"(r[3]) : "r"(addr));
}
static __device__ __forceinline__ void ldsm_x4_t(uint32_t* r, uint32_t addr) {
    asm volatile("ldmatrix.sync.aligned.m8n8.x4.trans.shared.b16 {%0,%1,%2,%3}, [%4];"
                 : "=r"(r[0]), "=r"(r[1]), "=r"(r[2]), "=r"(r[3]) : "r"(addr));
}
static __device__ __forceinline__ void mma_bf16(float* d, const uint32_t* a, const uint32_t* b) {
    asm volatile(
        "mma.sync.aligned.m16n8k16.row.col.f32.bf16.bf16.f32 "
        "{%0,%1,%2,%3}, {%4,%5,%6,%7}, {%8,%9}, {%0,%1,%2,%3};"
        : "+f"(d[0]), "+f"(d[1]), "+f"(d[2]), "+f"(d[3])
        : "r"(a[0]), "r"(a[1]), "r"(a[2]), "r"(a[3]), "r"(b[0]), "r"(b[1]));
}
// fp32 float4 -> (hi, lo) bf16 pairs packed as 2x uint2
static __device__ __forceinline__ void cvt4(const float4 x, uint2& hv, uint2& lv) {
    __nv_bfloat16 h0 = __float2bfloat16_rn(x.x);
    __nv_bfloat16 h1 = __float2bfloat16_rn(x.y);
    __nv_bfloat16 h2 = __float2bfloat16_rn(x.z);
    __nv_bfloat16 h3 = __float2bfloat16_rn(x.w);
    __nv_bfloat162 hp0 = __halves2bfloat162(h0, h1);
    __nv_bfloat162 hp1 = __halves2bfloat162(h2, h3);
    __nv_bfloat162 lp0 = __floats2bfloat162_rn(x.x - __bfloat162float(h0),
                                               x.y - __bfloat162float(h1));
    __nv_bfloat162 lp1 = __floats2bfloat162_rn(x.z - __bfloat162float(h2),
                                               x.w - __bfloat162float(h3));
    hv.x = *reinterpret_cast<uint32_t*>(&hp0);
    hv.y = *reinterpret_cast<uint32_t*>(&hp1);
    lv.x = *reinterpret_cast<uint32_t*>(&lp0);
    lv.y = *reinterpret_cast<uint32_t*>(&lp1);
}

// ===========================================================================
// K0: split fp32 -> (hi, lo) bf16.  which: 0=x, 1=w_qkv, 2=w_out
// ===========================================================================
__global__ void split_kernel(const float4* __restrict__ src, int n4, int which)
{
    __nv_bfloat16 *hi, *lo;
    if      (which == 0) { hi = g_xhi;  lo = g_xlo;  }
    else if (which == 1) { hi = g_wqhi; lo = g_wqlo; }
    else                 { hi = g_wohi; lo = g_wolo; }
    uint2* h2 = reinterpret_cast<uint2*>(hi);
    uint2* l2 = reinterpret_cast<uint2*>(lo);
    for (int i = blockIdx.x * blockDim.x + threadIdx.x; i < n4; i += gridDim.x * blockDim.x) {
        uint2 hv, lv;
        cvt4(src[i], hv, lv);
        h2[i] = hv;
        l2[i] = lv;
    }
}

// ===========================================================================
// K1/K6: bf16x3 HMMA GEMM — R5-proven config: tile 128x128, KC=64,
// 2-stage cp.async double buffer (2x64KB), wait_group 1.
// MODE 0: QKV (N=3072) epilogue scatters bucketed q/k/v
// MODE 1: OUT (N=1024), A gathered from bucketed g_ohi/g_olo, +bias
// ===========================================================================
#define SA_HI 0
#define SA_LO 16384
#define SB_HI 32768
#define SB_LO 49152
#define GBUF  65536
#define GEMM_SMEM_BYTES 131072

template<int MODE>
__global__ void __launch_bounds__(256)
mma_gemm_kernel(const float* __restrict__ bias, float* __restrict__ out)
{
    extern __shared__ char smx[];
    const uint32_t sbase = smem_u32(smx);
    const int tid  = threadIdx.x;
    const int wid  = tid >> 5, lane = tid & 31;
    const int m0   = blockIdx.x * 128;
    const int n0   = blockIdx.y * 128;
    const int wm   = (wid >> 2) * 64;
    const int wn   = (wid & 3) * 32;

    const __nv_bfloat16* Ah = (MODE == 0) ? g_xhi  : g_ohi;
    const __nv_bfloat16* Al = (MODE == 0) ? g_xlo  : g_olo;
    const __nv_bfloat16* Bh = (MODE == 0) ? g_wqhi : g_wohi;
    const __nv_bfloat16* Bl = (MODE == 0) ? g_wqlo : g_wolo;

    // ---- async tile loader: A/B (hi+lo) 128x64 bf16 each, swizzled --------
    auto load_chunk = [&](int c, int buf) {
        const int k0 = c * 64;
        const uint32_t sb = sbase + buf * GBUF;
        #pragma unroll
        for (int i = 0; i < 4; i++) {
            int idx = tid + i * 256;            // 0..1023
            int row = idx >> 3, c8 = idx & 7;   // row 0..127, 16B chunk 0..7
            uint32_t soff = sw128((uint32_t)(row * 128 + c8 * 16));
            size_t ga;
            if (MODE == 0) {
                ga = (size_t)(m0 + row) * 1024 + k0 + c8 * 8;
            } else {
                int k  = k0 + c8 * 8;
                int hh = k >> 7, dh = k & 127;
                int m  = m0 + row;
                int b2 = m >> 12, t = m & 4095;
                ga = (((size_t)((b2 * 8 + hh) * 64 + (t >> 6)) * 64) + (t & 63)) * 128 + dh;
            }
            cp16(sb + SA_HI + soff, Ah + ga);
            cp16(sb + SA_LO + soff, Al + ga);
            size_t gb = (size_t)(n0 + row) * 1024 + k0 + c8 * 8;
            cp16(sb + SB_HI + soff, Bh + gb);
            cp16(sb + SB_LO + soff, Bl + gb);
        }
    };

    float acc[4][4][4] = {};

    load_chunk(0, 0);
    cp_commit();

    for (int c = 0; c < 16; c++) {
        if (c + 1 < 16) load_chunk(c + 1, (c + 1) & 1);
        cp_commit();
        cp_wait1();
        __syncthreads();

        const uint32_t sb = sbase + (c & 1) * GBUF;
        #pragma unroll
        for (int ks = 0; ks < 4; ks++) {
            uint32_t ah[4][4], al[4][4];
            #pragma unroll
            for (int mt = 0; mt < 4; mt++) {
                uint32_t off = sw128((uint32_t)((wm + mt * 16 + (lane & 15)) * 128
                                                + ks * 32 + (lane >> 4) * 16));
                ldsm_x4(ah[mt], sb + SA_HI + off);
                ldsm_x4(al[mt], sb + SA_LO + off);
            }
            uint32_t bhf[2][4], blf[2][4];
            #pragma unroll
            for (int p = 0; p < 2; p++) {
                uint32_t off = sw128((uint32_t)((wn + p * 16 + ((lane >> 4) << 3) + (lane & 7)) * 128
                                                + ks * 32 + (((lane >> 3) & 1) << 4)));
                ldsm_x4(bhf[p], sb + SB_HI + off);
                ldsm_x4(blf[p], sb + SB_LO + off);
            }
            #pragma unroll
            for (int mt = 0; mt < 4; mt++)
                #pragma unroll
                for (int nt = 0; nt < 4; nt++) {
                    const uint32_t* bhp = &bhf[nt >> 1][(nt & 1) * 2];
                    const uint32_t* blp = &blf[nt >> 1][(nt & 1) * 2];
                    mma_bf16(acc[mt][nt], ah[mt], bhp);
                    mma_bf16(acc[mt][nt], ah[mt], blp);
                    mma_bf16(acc[mt][nt], al[mt], bhp);
                }
        }
        __syncthreads();
    }

    // ---- epilogue: fragment layout (g=lane>>2, t2=(lane&3)*2) -------------
    const int g  = lane >> 2;
    const int t2 = (lane & 3) * 2;
    #pragma unroll
    for (int mt = 0; mt < 4; mt++)
        #pragma unroll
        for (int nt = 0; nt < 4; nt++) {
            int col = n0 + wn + nt * 8 + t2;
            #pragma unroll
            for (int half = 0; half < 2; half++) {
                int row = m0 + wm + mt * 16 + g + half * 8;
                float v0 = acc[mt][nt][half * 2 + 0];
                float v1 = acc[mt][nt][half * 2 + 1];
                if (MODE == 0) {
                    int which = col >> 10;
                    float* dst = (which == 0) ? g_q : (which == 1) ? g_k : g_v;
                    int h  = (col >> 7) & 7, dh = col & 127;
                    int b2 = row >> 12, t = row & 4095;
                    size_t o = (((size_t)((b2 * 8 + h) * 64 + (t >> 6)) * 64) + (t & 63)) * 128 + dh;
                    *reinterpret_cast<float2*>(&dst[o]) = make_float2(v0, v1);
                } else {
                    *reinterpret_cast<float2*>(&out[(size_t)row * 1024 + col]) =
                        make_float2(v0 + bias[col], v1 + bias[col + 1]);
                }
            }
        }
}

// ===========================================================================
// K2: bucket key summaries
// ===========================================================================
__global__ void bucket_sum_kernel()
{
    const int bu = blockIdx.x;
    const int dh = threadIdx.x;
    const float* src = &g_k[(size_t)bu * TILE_ELEMS];
    float s = 0.f;
    #pragma unroll
    for (int p = 0; p < 64; p++) s += src[p * 128 + dh];
    g_bkr[bu * 128 + dh] = s;
}

// ===========================================================================
// K3: sorting logits + gumbel + 5 sinkhorn iterations + tril(exp(.),-1)
// ===========================================================================
__global__ void __launch_bounds__(256)
sinkhorn_kernel(const float* __restrict__ sort_w, const float* __restrict__ noise_u)
{
    __shared__ float R[64][65];
    const int bh  = blockIdx.x;
    const int h   = bh & 7;
    const int tid = threadIdx.x;

    for (int i = tid; i < 4096; i += 256) {
        int u = i >> 6, v = i & 63;
        const float* br = &g_bkr[bh * 8192 + u * 128];
        const float* ew = &sort_w[h * 8192];
        float s = 0.f;
        #pragma unroll 8
        for (int d = 0; d < 128; d++) s += br[d] * ew[d * 64 + v];
        float r  = logf(fmaxf(s, 0.f) + 1e-6f);
        float nu = noise_u[bh * 4096 + i];
        float gb = -logf(-logf(nu + 1e-4f) + 1e-4f);
        R[u][v] = (r + gb) * (1.0f / 0.75f);
    }
    __syncthreads();

    const int warp = tid >> 5, lane = tid & 31;
    for (int it = 0; it < 5; it++) {
        for (int r = warp; r < 64; r += 8) {
            float x0 = R[r][lane], x1 = R[r][lane + 32];
            float m = fmaxf(x0, x1);
            #pragma unroll
            for (int o = 16; o; o >>= 1) m = fmaxf(m, __shfl_xor_sync(0xffffffffu, m, o));
            float s = expf(x0 - m) + expf(x1 - m);
            #pragma unroll
            for (int o = 16; o; o >>= 1) s += __shfl_xor_sync(0xffffffffu, s, o);
            float l = m + logf(s);
            R[r][lane]      = x0 - l;
            R[r][lane + 32] = x1 - l;
        }
        __syncthreads();
        if (tid < 64) {
            float m = -INFINITY;
            for (int u2 = 0; u2 < 64; u2++) m = fmaxf(m, R[u2][tid]);
            float s = 0.f;
            for (int u2 = 0; u2 < 64; u2++) s += expf(R[u2][tid] - m);
            float l = m + logf(s);
            for (int u2 = 0; u2 < 64; u2++) R[u2][tid] -= l;
        }
        __syncthreads();
    }
    for (int i = tid; i < 4096; i += 256) {
        int u = i >> 6, v = i & 63;
        g_R[bh * 4096 + i] = (u > v) ? expf(R[u][v]) : 0.f;
    }
}

// ===========================================================================
// K4: soft permute as tensor-core GEMM: kre[bh] = R[bh](64x64) @ k[bh](64x8192)
// Each CTA: one bh + one 256-column slice; k/v tiles read exactly ONCE.
// ===========================================================================
#define PSM_RHI  0
#define PSM_RLO  8192
#define PSM_K    16384              // 64KB: Khi 32KB | Klo 32KB (reused as fp32 stage)
#define PERM_SMEM_BYTES (16384 + 65536)

__global__ void __launch_bounds__(256)
permute_kernel()
{
    extern __shared__ char psm[];
    const uint32_t sbase = smem_u32(psm);
    const int tid  = threadIdx.x;
    const int wid  = tid >> 5, lane = tid & 31;
    const int bh   = blockIdx.x >> 5;
    const int col0 = (blockIdx.x & 31) * 256;
    const int mt   = wid & 3;         // m16 block of the 64 u-rows
    const int nh   = wid >> 2;        // 128-col half of the 256-col slice
    const size_t bhbase = (size_t)bh * 524288;   // 64 * 8192

    // ---- load R[bh] -> bf16 hi/lo, sw128 (128B rows) ----------------------
    for (int i = tid; i < 1024; i += 256) {       // 4096 floats / 4
        int row = i >> 4, c4 = i & 15;
        float4 x = *reinterpret_cast<const float4*>(&g_R[bh * 4096 + row * 64 + c4 * 4]);
        uint2 hv, lv; cvt4(x, hv, lv);
        uint32_t off = sw128((uint32_t)(row * 128 + c4 * 8));
        *reinterpret_cast<uint2*>(psm + PSM_RHI + off) = hv;
        *reinterpret_cast<uint2*>(psm + PSM_RLO + off) = lv;
    }

    const float* srcs[2] = {g_k, g_v};
    float*       dsts[2] = {g_kre, g_vre};

    for (int ph = 0; ph < 2; ph++) {
        const float* src = srcs[ph];
        float*       dst = dsts[ph];

        __syncthreads();
        for (int i = tid; i < 4096; i += 256) {   // 64 rows x 64 float4
            int v = i >> 6, c4 = i & 63;
            float4 x = *reinterpret_cast<const float4*>(&src[bhbase + (size_t)v * 8192 + col0 + c4 * 4]);
            uint2 hv, lv; cvt4(x, hv, lv);
            uint32_t off = swzK((uint32_t)(v * 512 + c4 * 8));
            *reinterpret_cast<uint2*>(psm + PSM_K + off)         = hv;
            *reinterpret_cast<uint2*>(psm + PSM_K + 32768 + off) = lv;
        }
        __syncthreads();

        float acc[16][4];
        #pragma unroll
        for (int f = 0; f < 16; f++)
            #pragma unroll
            for (int e = 0; e < 4; e++) acc[f][e] = 0.f;

        #pragma unroll
        for (int ks = 0; ks < 4; ks++) {          // v0 = ks*16
            uint32_t ahf[4], alf[4];
            {
                int u = mt * 16 + (lane & 15);
                uint32_t off = sw128((uint32_t)(u * 128 + ks * 32 + (lane >> 4) * 16));
                ldsm_x4(ahf, sbase + PSM_RHI + off);
                ldsm_x4(alf, sbase + PSM_RLO + off);
            }
            #pragma unroll
            for (int j2 = 0; j2 < 8; j2++) {      // n16 blocks within 128 cols
                int n0 = nh * 128 + j2 * 16;
                uint32_t off = swzK((uint32_t)((ks * 16 + (lane & 15)) * 512
                                               + (n0 + (lane >> 4) * 8) * 2));
                uint32_t khf[4], klf[4];
                ldsm_x4_t(khf, sbase + PSM_K + off);
                ldsm_x4_t(klf, sbase + PSM_K + 32768 + off);
                #pragma unroll
                for (int nb = 0; nb < 2; nb++) {
                    float* a = acc[j2 * 2 + nb];
                    mma_bf16(a, ahf, &khf[nb * 2]);
                    mma_bf16(a, ahf, &klf[nb * 2]);
                    mma_bf16(a, alf, &khf[nb * 2]);
                }
            }
        }
        __syncthreads();   // all ldsm done before stage overwrites K region

        float* stage = reinterpret_cast<float*>(psm + PSM_K);
        const int g2 = lane >> 2, t2 = (lane & 3) * 2;
        #pragma unroll
        for (int j2 = 0; j2 < 8; j2++)
            #pragma unroll
            for (int nb = 0; nb < 2; nb++) {
                int col = nh * 128 + j2 * 16 + nb * 8 + t2;
                #pragma unroll
                for (int half = 0; half < 2; half++) {
                    int u = mt * 16 + g2 + half * 8;
                    *reinterpret_cast<float2*>(&stage[u * 256 + col]) =
                        make_float2(acc[j2 * 2 + nb][half * 2 + 0],
                                    acc[j2 * 2 + nb][half * 2 + 1]);
                }
            }
        __syncthreads();
        for (int i = tid; i < 4096; i += 256) {
            int u = i >> 6, c4 = i & 63;
            *reinterpret_cast<float4*>(&dst[bhbase + (size_t)u * 8192 + col0 + c4 * 4]) =
                *reinterpret_cast<const float4*>(&stage[u * 256 + c4 * 4]);
        }
    }
}

// ===========================================================================
// K5: bucketed attention, one CTA per (bh,u); epilogue writes bf16 hi/lo
// directly for the output GEMM (no fp32 g_o round-trip).
// ===========================================================================
#define ATTN_SMEM_FLOATS (8192 + 128 * 132 + 64 * 132)
#define ATTN_SMEM_BYTES  (ATTN_SMEM_FLOATS * 4)

__global__ void __launch_bounds__(256)
attn_kernel()
{
    extern __shared__ float sm[];
    float* qs = sm;
    float* kt = sm + 8192;
    float* ds = sm + 8192 + 128 * 132;

    const int blk = blockIdx.x;
    const int tid = threadIdx.x;
    const size_t base = (size_t)blk * TILE_ELEMS;

    for (int i = tid; i < 8192; i += 256) qs[i] = g_q[base + i];
    for (int i = tid; i < 8192; i += 256) {
        int j = i >> 7, d = i & 127;
        kt[d * 132 + j] = g_kre[base + i];
    }
    for (int i = tid; i < 8192; i += 256) {
        int j = i >> 7, d = i & 127;
        kt[d * 132 + 64 + j] = g_k[base + i];
    }
    __syncthreads();

    const int tx = tid & 15, ty = tid >> 4;
    const int r0 = ty * 4, c0 = tx * 8;

    float acc[4][8] = {};
    for (int d = 0; d < 128; d++) {
        float a[4];
        #pragma unroll
        for (int i = 0; i < 4; i++) a[i] = qs[(r0 + i) * 128 + d];
        float4 b0 = *(float4*)&kt[d * 132 + c0];
        float4 b1 = *(float4*)&kt[d * 132 + c0 + 4];
        float b[8] = {b0.x, b0.y, b0.z, b0.w, b1.x, b1.y, b1.z, b1.w};
        #pragma unroll
        for (int i = 0; i < 4; i++)
            #pragma unroll
            for (int j = 0; j < 8; j++)
                acc[i][j] = fmaf(a[i], b[j], acc[i][j]);
    }
    #pragma unroll
    for (int i = 0; i < 4; i++)
        #pragma unroll
        for (int j = 0; j < 8; j++)
            ds[(r0 + i) * 132 + c0 + j] = acc[i][j] * 0.03125f;
    __syncthreads();

    for (int i = tid; i < 8192; i += 256) {
        int j = i >> 7, e = i & 127;
        kt[j * 132 + e] = g_vre[base + i];
    }
    for (int i = tid; i < 8192; i += 256) {
        int j = i >> 7, e = i & 127;
        kt[(j + 64) * 132 + e] = g_v[base + i];
    }
    if (tid < 64) {
        float m = -INFINITY;
        for (int j = 0; j < 128; j++) m = fmaxf(m, ds[tid * 132 + j]);
        float s = 0.f;
        for (int j = 0; j < 128; j++) {
            float e = expf(ds[tid * 132 + j] - m);
            ds[tid * 132 + j] = e;
            s += e;
        }
        float inv = 1.f / s;
        for (int j = 0; j < 128; j++) ds[tid * 132 + j] *= inv;
    }
    __syncthreads();

    float o[4][8] = {};
    for (int j = 0; j < 128; j++) {
        float a[4];
        #pragma unroll
        for (int i = 0; i < 4; i++) a[i] = ds[(r0 + i) * 132 + j];
        float4 b0 = *(float4*)&kt[j * 132 + c0];
        float4 b1 = *(float4*)&kt[j * 132 + c0 + 4];
        float b[8] = {b0.x, b0.y, b0.z, b0.w, b1.x, b1.y, b1.z, b1.w};
        #pragma unroll
        for (int i = 0; i < 4; i++)
            #pragma unroll
            for (int jj = 0; jj < 8; jj++)
                o[i][jj] = fmaf(a[i], b[jj], o[i][jj]);
    }
    #pragma unroll
    for (int i = 0; i < 4; i++) {
        size_t off = base + (r0 + i) * 128 + c0;
        float4 o0 = make_float4(o[i][0], o[i][1], o[i][2], o[i][3]);
        float4 o1 = make_float4(o[i][4], o[i][5], o[i][6], o[i][7]);
        uint2 hv, lv;
        cvt4(o0, hv, lv);
        *reinterpret_cast<uint2*>(&g_ohi[off]) = hv;
        *reinterpret_cast<uint2*>(&g_olo[off]) = lv;
        cvt4(o1, hv, lv);
        *reinterpret_cast<uint2*>(&g_ohi[off + 4]) = hv;
        *reinterpret_cast<uint2*>(&g_olo[off + 4]) = lv;
    }
}

// ===========================================================================
extern "C" void kernel_launch(void* const* d_in, const int* in_sizes, int n_in,
                              void* d_out, int out_size)
{
    (void)in_sizes; (void)n_in; (void)out_size;
    const float* x      = (const float*)d_in[0];
    const float* w_qkv  = (const float*)d_in[1];
    const float* sort_w = (const float*)d_in[2];
    const float* w_out  = (const float*)d_in[3];
    const float* b_out  = (const float*)d_in[4];
    const float* noise  = (const float*)d_in[5];
    float* out = (float*)d_out;

    cudaFuncSetAttribute(attn_kernel, cudaFuncAttributeMaxDynamicSharedMemorySize,
                         ATTN_SMEM_BYTES);
    cudaFuncSetAttribute(mma_gemm_kernel<0>, cudaFuncAttributeMaxDynamicSharedMemorySize,
                         GEMM_SMEM_BYTES);
    cudaFuncSetAttribute(mma_gemm_kernel<1>, cudaFuncAttributeMaxDynamicSharedMemorySize,
                         GEMM_SMEM_BYTES);
    cudaFuncSetAttribute(permute_kernel, cudaFuncAttributeMaxDynamicSharedMemorySize,
                         PERM_SMEM_BYTES);

    split_kernel<<<4096, 256>>>((const float4*)x,     4194304, 0);
    split_kernel<<<3072, 256>>>((const float4*)w_qkv,  786432, 1);
    split_kernel<<<1024, 256>>>((const float4*)w_out,  262144, 2);

    mma_gemm_kernel<0><<<dim3(128, 24), 256, GEMM_SMEM_BYTES>>>(nullptr, nullptr);

    bucket_sum_kernel<<<2048, 128>>>();
    sinkhorn_kernel<<<32, 256>>>(sort_w, noise);
    permute_kernel<<<1024, 256, PERM_SMEM_BYTES>>>();
    attn_kernel<<<2048, 256, ATTN_SMEM_BYTES>>>();

    mma_gemm_kernel<1><<<dim3(128, 8), 256, GEMM_SMEM_BYTES>>>(b_out, out);
}

// round 11
// speedup vs baseline: 2.8740x; 1.2118x over previous
#include <cuda_runtime.h>
#include <cuda_bf16.h>
#include <math.h>
#include <stdint.h>

// Problem constants: B=4, T=4096, D=1024, H=8, BUCKETS=64, BSZ=64, DH=128
#define TILE_ELEMS    8192          // BSZ * DH
#define BIG_ELEMS     16777216      // 2048 * 8192

// -------- device scratch (static globals: allocation-free, graph-safe) -----
// q/k/v and permuted k/v live ONLY as bf16 (hi,lo) pairs end-to-end.
__device__ __nv_bfloat16 g_qhi [BIG_ELEMS];
__device__ __nv_bfloat16 g_qlo [BIG_ELEMS];
__device__ __nv_bfloat16 g_khi [BIG_ELEMS];
__device__ __nv_bfloat16 g_klo [BIG_ELEMS];
__device__ __nv_bfloat16 g_vhi [BIG_ELEMS];
__device__ __nv_bfloat16 g_vlo [BIG_ELEMS];
__device__ __nv_bfloat16 g_krehi[BIG_ELEMS];
__device__ __nv_bfloat16 g_krelo[BIG_ELEMS];
__device__ __nv_bfloat16 g_vrehi[BIG_ELEMS];
__device__ __nv_bfloat16 g_vrelo[BIG_ELEMS];
__device__ float g_bkr[32 * 64 * 128];
__device__ float g_R  [32 * 64 * 64];

__device__ __nv_bfloat16 g_xhi [BIG_ELEMS];
__device__ __nv_bfloat16 g_xlo [BIG_ELEMS];
__device__ __nv_bfloat16 g_wqhi[3145728];
__device__ __nv_bfloat16 g_wqlo[3145728];
__device__ __nv_bfloat16 g_wohi[1048576];
__device__ __nv_bfloat16 g_wolo[1048576];
__device__ __nv_bfloat16 g_ohi [BIG_ELEMS];
__device__ __nv_bfloat16 g_olo [BIG_ELEMS];

// ===========================================================================
// helpers (portable PTX, sm_80-era features only)
// ===========================================================================
static __device__ __forceinline__ uint32_t smem_u32(const void* p) {
    uint32_t a;
    asm("{ .reg .u64 t; cvta.to.shared.u64 t, %1; cvt.u32.u64 %0, t; }"
        : "=r"(a) : "l"(p));
    return a;
}
static __device__ __forceinline__ uint32_t sw128(uint32_t o) {   // 128B-pitch rows
    return o ^ ((o >> 3) & 0x70);
}
static __device__ __forceinline__ uint32_t swz256(uint32_t o) {  // 256B-pitch rows
    return o ^ ((o >> 4) & 0x70);
}
static __device__ __forceinline__ uint32_t swzK(uint32_t o) {    // 512B-pitch rows
    return o ^ ((o >> 5) & 0x70);
}
static __device__ __forceinline__ void cp16(uint32_t sdst, const void* gsrc) {
    asm volatile("cp.async.cg.shared.global [%0], [%1], 16;"
                 :: "r"(sdst), "l"(__cvta_generic_to_global(gsrc)) : "memory");
}
static __device__ __forceinline__ void cp_commit() {
    asm volatile("cp.async.commit_group;" ::: "memory");
}
static __device__ __forceinline__ void cp_wait1() {
    asm volatile("cp.async.wait_group 1;" ::: "memory");
}
static __device__ __forceinline__ void ldsm_x4(uint32_t* r, uint32_t addr) {
    asm volatile("ldmatrix.sync.aligned.m8n8.x4.shared.b16 {%0,%1,%2,%3}, [%4];"
                 : "=r"(r[0]), "=r"(r[1]), "=r"(r[2]), "=r"(r[3]) : "r"(addr));
}
static __device__ __forceinline__ void ldsm_x4_t(uint32_t* r, uint32_t addr) {
    asm volatile("ldmatrix.sync.aligned.m8n8.x4.trans.shared.b16 {%0,%1,%2,%3}, [%4];"
                 : "=r"(r[0]), "=r"(r[1]), "=r"(r[2]), "=r"(r[3]) : "r"(addr));
}
static __device__ __forceinline__ void mma_bf16(float* d, const uint32_t* a, const uint32_t* b) {
    asm volatile(
        "mma.sync.aligned.m16n8k16.row.col.f32.bf16.bf16.f32 "
        "{%0,%1,%2,%3}, {%4,%5,%6,%7}, {%8,%9}, {%0,%1,%2,%3};"
        : "+f"(d[0]), "+f"(d[1]), "+f"(d[2]), "+f"(d[3])
        : "r"(a[0]), "r"(a[1]), "r"(a[2]), "r"(a[3]), "r"(b[0]), "r"(b[1]));
}
// fp32 pair -> packed bf16 (hi, lo)
static __device__ __forceinline__ void cvt2(float v0, float v1, uint32_t& h, uint32_t& l) {
    __nv_bfloat16 h0 = __float2bfloat16_rn(v0);
    __nv_bfloat16 h1 = __float2bfloat16_rn(v1);
    __nv_bfloat162 hp = __halves2bfloat162(h0, h1);
    __nv_bfloat162 lp = __floats2bfloat162_rn(v0 - __bfloat162float(h0),
                                              v1 - __bfloat162float(h1));
    h = *reinterpret_cast<uint32_t*>(&hp);
    l = *reinterpret_cast<uint32_t*>(&lp);
}
// fp32 float4 -> (hi, lo) bf16 pairs packed as 2x uint2
static __device__ __forceinline__ void cvt4(const float4 x, uint2& hv, uint2& lv) {
    cvt2(x.x, x.y, hv.x, lv.x);
    cvt2(x.z, x.w, hv.y, lv.y);
}

// ===========================================================================
// K0: split fp32 -> (hi, lo) bf16.  which: 0=x, 1=w_qkv, 2=w_out
// ===========================================================================
__global__ void split_kernel(const float4* __restrict__ src, int n4, int which)
{
    __nv_bfloat16 *hi, *lo;
    if      (which == 0) { hi = g_xhi;  lo = g_xlo;  }
    else if (which == 1) { hi = g_wqhi; lo = g_wqlo; }
    else                 { hi = g_wohi; lo = g_wolo; }
    uint2* h2 = reinterpret_cast<uint2*>(hi);
    uint2* l2 = reinterpret_cast<uint2*>(lo);
    for (int i = blockIdx.x * blockDim.x + threadIdx.x; i < n4; i += gridDim.x * blockDim.x) {
        uint2 hv, lv;
        cvt4(src[i], hv, lv);
        h2[i] = hv;
        l2[i] = lv;
    }
}

// ===========================================================================
// K1/K6: bf16x3 HMMA GEMM — proven config: tile 128x128, KC=64, 2-stage
// cp.async double buffer. MODE 0: QKV (N=3072), epilogue scatters bucketed
// q/k/v as bf16 hi/lo. MODE 1: OUT (N=1024), A = g_ohi/g_olo, fp32 out +bias.
// ===========================================================================
#define SA_HI 0
#define SA_LO 16384
#define SB_HI 32768
#define SB_LO 49152
#define GBUF  65536
#define GEMM_SMEM_BYTES 131072

template<int MODE>
__global__ void __launch_bounds__(256)
mma_gemm_kernel(const float* __restrict__ bias, float* __restrict__ out)
{
    extern __shared__ char smx[];
    const uint32_t sbase = smem_u32(smx);
    const int tid  = threadIdx.x;
    const int wid  = tid >> 5, lane = tid & 31;
    const int m0   = blockIdx.x * 128;
    const int n0   = blockIdx.y * 128;
    const int wm   = (wid >> 2) * 64;
    const int wn   = (wid & 3) * 32;

    const __nv_bfloat16* Ah = (MODE == 0) ? g_xhi  : g_ohi;
    const __nv_bfloat16* Al = (MODE == 0) ? g_xlo  : g_olo;
    const __nv_bfloat16* Bh = (MODE == 0) ? g_wqhi : g_wohi;
    const __nv_bfloat16* Bl = (MODE == 0) ? g_wqlo : g_wolo;

    auto load_chunk = [&](int c, int buf) {
        const int k0 = c * 64;
        const uint32_t sb = sbase + buf * GBUF;
        #pragma unroll
        for (int i = 0; i < 4; i++) {
            int idx = tid + i * 256;            // 0..1023
            int row = idx >> 3, c8 = idx & 7;   // row 0..127, 16B chunk 0..7
            uint32_t soff = sw128((uint32_t)(row * 128 + c8 * 16));
            size_t ga;
            if (MODE == 0) {
                ga = (size_t)(m0 + row) * 1024 + k0 + c8 * 8;
            } else {
                int k  = k0 + c8 * 8;
                int hh = k >> 7, dh = k & 127;
                int m  = m0 + row;
                int b2 = m >> 12, t = m & 4095;
                ga = (((size_t)((b2 * 8 + hh) * 64 + (t >> 6)) * 64) + (t & 63)) * 128 + dh;
            }
            cp16(sb + SA_HI + soff, Ah + ga);
            cp16(sb + SA_LO + soff, Al + ga);
            size_t gb = (size_t)(n0 + row) * 1024 + k0 + c8 * 8;
            cp16(sb + SB_HI + soff, Bh + gb);
            cp16(sb + SB_LO + soff, Bl + gb);
        }
    };

    float acc[4][4][4] = {};

    load_chunk(0, 0);
    cp_commit();

    for (int c = 0; c < 16; c++) {
        if (c + 1 < 16) load_chunk(c + 1, (c + 1) & 1);
        cp_commit();
        cp_wait1();
        __syncthreads();

        const uint32_t sb = sbase + (c & 1) * GBUF;
        #pragma unroll
        for (int ks = 0; ks < 4; ks++) {
            uint32_t ah[4][4], al[4][4];
            #pragma unroll
            for (int mt = 0; mt < 4; mt++) {
                uint32_t off = sw128((uint32_t)((wm + mt * 16 + (lane & 15)) * 128
                                                + ks * 32 + (lane >> 4) * 16));
                ldsm_x4(ah[mt], sb + SA_HI + off);
                ldsm_x4(al[mt], sb + SA_LO + off);
            }
            uint32_t bhf[2][4], blf[2][4];
            #pragma unroll
            for (int p = 0; p < 2; p++) {
                uint32_t off = sw128((uint32_t)((wn + p * 16 + ((lane >> 4) << 3) + (lane & 7)) * 128
                                                + ks * 32 + (((lane >> 3) & 1) << 4)));
                ldsm_x4(bhf[p], sb + SB_HI + off);
                ldsm_x4(blf[p], sb + SB_LO + off);
            }
            #pragma unroll
            for (int mt = 0; mt < 4; mt++)
                #pragma unroll
                for (int nt = 0; nt < 4; nt++) {
                    const uint32_t* bhp = &bhf[nt >> 1][(nt & 1) * 2];
                    const uint32_t* blp = &blf[nt >> 1][(nt & 1) * 2];
                    mma_bf16(acc[mt][nt], ah[mt], bhp);
                    mma_bf16(acc[mt][nt], ah[mt], blp);
                    mma_bf16(acc[mt][nt], al[mt], bhp);
                }
        }
        __syncthreads();
    }

    const int g  = lane >> 2;
    const int t2 = (lane & 3) * 2;
    #pragma unroll
    for (int mt = 0; mt < 4; mt++)
        #pragma unroll
        for (int nt = 0; nt < 4; nt++) {
            int col = n0 + wn + nt * 8 + t2;
            #pragma unroll
            for (int half = 0; half < 2; half++) {
                int row = m0 + wm + mt * 16 + g + half * 8;
                float v0 = acc[mt][nt][half * 2 + 0];
                float v1 = acc[mt][nt][half * 2 + 1];
                if (MODE == 0) {
                    int which = col >> 10;
                    __nv_bfloat16 *dh_, *dl_;
                    if      (which == 0) { dh_ = g_qhi; dl_ = g_qlo; }
                    else if (which == 1) { dh_ = g_khi; dl_ = g_klo; }
                    else                 { dh_ = g_vhi; dl_ = g_vlo; }
                    int h  = (col >> 7) & 7, dh = col & 127;
                    int b2 = row >> 12, t = row & 4095;
                    size_t o = (((size_t)((b2 * 8 + h) * 64 + (t >> 6)) * 64) + (t & 63)) * 128 + dh;
                    uint32_t hv, lv;
                    cvt2(v0, v1, hv, lv);
                    *reinterpret_cast<uint32_t*>(&dh_[o]) = hv;
                    *reinterpret_cast<uint32_t*>(&dl_[o]) = lv;
                } else {
                    *reinterpret_cast<float2*>(&out[(size_t)row * 1024 + col]) =
                        make_float2(v0 + bias[col], v1 + bias[col + 1]);
                }
            }
        }
}

// ===========================================================================
// K2: bucket key summaries  bkr[bh,u,dh] = sum_p (khi+klo)[bh,u,p,dh]
// ===========================================================================
__global__ void bucket_sum_kernel()
{
    const int bu = blockIdx.x;
    const int dh = threadIdx.x;
    const size_t base = (size_t)bu * TILE_ELEMS;
    float s = 0.f;
    #pragma unroll
    for (int p = 0; p < 64; p++) {
        s += __bfloat162float(g_khi[base + p * 128 + dh]);
        s += __bfloat162float(g_klo[base + p * 128 + dh]);
    }
    g_bkr[bu * 128 + dh] = s;
}

// ===========================================================================
// K3: sorting logits + gumbel + 5 sinkhorn iterations + tril(exp(.),-1)
// ===========================================================================
__global__ void __launch_bounds__(256)
sinkhorn_kernel(const float* __restrict__ sort_w, const float* __restrict__ noise_u)
{
    __shared__ float R[64][65];
    const int bh  = blockIdx.x;
    const int h   = bh & 7;
    const int tid = threadIdx.x;

    for (int i = tid; i < 4096; i += 256) {
        int u = i >> 6, v = i & 63;
        const float* br = &g_bkr[bh * 8192 + u * 128];
        const float* ew = &sort_w[h * 8192];
        float s = 0.f;
        #pragma unroll 8
        for (int d = 0; d < 128; d++) s += br[d] * ew[d * 64 + v];
        float r  = logf(fmaxf(s, 0.f) + 1e-6f);
        float nu = noise_u[bh * 4096 + i];
        float gb = -logf(-logf(nu + 1e-4f) + 1e-4f);
        R[u][v] = (r + gb) * (1.0f / 0.75f);
    }
    __syncthreads();

    const int warp = tid >> 5, lane = tid & 31;
    for (int it = 0; it < 5; it++) {
        for (int r = warp; r < 64; r += 8) {
            float x0 = R[r][lane], x1 = R[r][lane + 32];
            float m = fmaxf(x0, x1);
            #pragma unroll
            for (int o = 16; o; o >>= 1) m = fmaxf(m, __shfl_xor_sync(0xffffffffu, m, o));
            float s = expf(x0 - m) + expf(x1 - m);
            #pragma unroll
            for (int o = 16; o; o >>= 1) s += __shfl_xor_sync(0xffffffffu, s, o);
            float l = m + logf(s);
            R[r][lane]      = x0 - l;
            R[r][lane + 32] = x1 - l;
        }
        __syncthreads();
        if (tid < 64) {
            float m = -INFINITY;
            for (int u2 = 0; u2 < 64; u2++) m = fmaxf(m, R[u2][tid]);
            float s = 0.f;
            for (int u2 = 0; u2 < 64; u2++) s += expf(R[u2][tid] - m);
            float l = m + logf(s);
            for (int u2 = 0; u2 < 64; u2++) R[u2][tid] -= l;
        }
        __syncthreads();
    }
    for (int i = tid; i < 4096; i += 256) {
        int u = i >> 6, v = i & 63;
        g_R[bh * 4096 + i] = (u > v) ? expf(R[u][v]) : 0.f;
    }
}

// ===========================================================================
// K4: soft permute as HMMA GEMM: kre = R(64x64) @ k(64x8192), bf16 in/out.
// Tile loads are raw 16B copies (operands already split); epilogue converts
// fp32 accumulators to hi/lo once.
// ===========================================================================
#define PSM_RHI  0
#define PSM_RLO  8192
#define PSM_K    16384              // Khi 32KB | Klo 32KB (reused as hi/lo stage)
#define PERM_SMEM_BYTES (16384 + 65536)

__global__ void __launch_bounds__(256)
permute_kernel()
{
    extern __shared__ char psm[];
    const uint32_t sbase = smem_u32(psm);
    const int tid  = threadIdx.x;
    const int wid  = tid >> 5, lane = tid & 31;
    const int bh   = blockIdx.x >> 5;
    const int col0 = (blockIdx.x & 31) * 256;
    const int mt   = wid & 3;
    const int nh   = wid >> 2;
    const size_t bhbase = (size_t)bh * 524288;

    for (int i = tid; i < 1024; i += 256) {
        int row = i >> 4, c4 = i & 15;
        float4 x = *reinterpret_cast<const float4*>(&g_R[bh * 4096 + row * 64 + c4 * 4]);
        uint2 hv, lv; cvt4(x, hv, lv);
        uint32_t off = sw128((uint32_t)(row * 128 + c4 * 8));
        *reinterpret_cast<uint2*>(psm + PSM_RHI + off) = hv;
        *reinterpret_cast<uint2*>(psm + PSM_RLO + off) = lv;
    }

    for (int ph = 0; ph < 2; ph++) {
        const __nv_bfloat16* shi = ph ? g_vhi : g_khi;
        const __nv_bfloat16* slo = ph ? g_vlo : g_klo;
        __nv_bfloat16* dhi = ph ? g_vrehi : g_krehi;
        __nv_bfloat16* dlo = ph ? g_vrelo : g_krelo;

        __syncthreads();
        for (int i = tid; i < 2048; i += 256) {     // 64 rows x 32 chunks(16B)
            int v = i >> 5, c8 = i & 31;
            uint32_t off = swzK((uint32_t)(v * 512 + c8 * 16));
            size_t ga = bhbase + (size_t)v * 8192 + col0 + c8 * 8;
            *reinterpret_cast<uint4*>(psm + PSM_K + off)         = *reinterpret_cast<const uint4*>(&shi[ga]);
            *reinterpret_cast<uint4*>(psm + PSM_K + 32768 + off) = *reinterpret_cast<const uint4*>(&slo[ga]);
        }
        __syncthreads();

        float acc[16][4];
        #pragma unroll
        for (int f = 0; f < 16; f++)
            #pragma unroll
            for (int e = 0; e < 4; e++) acc[f][e] = 0.f;

        #pragma unroll
        for (int ks = 0; ks < 4; ks++) {
            uint32_t ahf[4], alf[4];
            {
                int u = mt * 16 + (lane & 15);
                uint32_t off = sw128((uint32_t)(u * 128 + ks * 32 + (lane >> 4) * 16));
                ldsm_x4(ahf, sbase + PSM_RHI + off);
                ldsm_x4(alf, sbase + PSM_RLO + off);
            }
            #pragma unroll
            for (int j2 = 0; j2 < 8; j2++) {
                int n0 = nh * 128 + j2 * 16;
                uint32_t off = swzK((uint32_t)((ks * 16 + (lane & 15)) * 512
                                               + (n0 + (lane >> 4) * 8) * 2));
                uint32_t khf[4], klf[4];
                ldsm_x4_t(khf, sbase + PSM_K + off);
                ldsm_x4_t(klf, sbase + PSM_K + 32768 + off);
                #pragma unroll
                for (int nb = 0; nb < 2; nb++) {
                    float* a = acc[j2 * 2 + nb];
                    mma_bf16(a, ahf, &khf[nb * 2]);
                    mma_bf16(a, ahf, &klf[nb * 2]);
                    mma_bf16(a, alf, &khf[nb * 2]);
                }
            }
        }
        __syncthreads();

        __nv_bfloat16* sthi = reinterpret_cast<__nv_bfloat16*>(psm + PSM_K);
        __nv_bfloat16* stlo = reinterpret_cast<__nv_bfloat16*>(psm + PSM_K + 32768);
        const int g2 = lane >> 2, t2 = (lane & 3) * 2;
        #pragma unroll
        for (int j2 = 0; j2 < 8; j2++)
            #pragma unroll
            for (int nb = 0; nb < 2; nb++) {
                int col = nh * 128 + j2 * 16 + nb * 8 + t2;
                #pragma unroll
                for (int half = 0; half < 2; half++) {
                    int u = mt * 16 + g2 + half * 8;
                    uint32_t hv, lv;
                    cvt2(acc[j2 * 2 + nb][half * 2 + 0], acc[j2 * 2 + nb][half * 2 + 1], hv, lv);
                    *reinterpret_cast<uint32_t*>(&sthi[u * 256 + col]) = hv;
                    *reinterpret_cast<uint32_t*>(&stlo[u * 256 + col]) = lv;
                }
            }
        __syncthreads();
        for (int i = tid; i < 2048; i += 256) {
            int u = i >> 5, c8 = i & 31;
            size_t ga = bhbase + (size_t)u * 8192 + col0 + c8 * 8;
            *reinterpret_cast<uint4*>(&dhi[ga]) = *reinterpret_cast<uint4*>((char*)sthi + u * 512 + c8 * 16);
            *reinterpret_cast<uint4*>(&dlo[ga]) = *reinterpret_cast<uint4*>((char*)stlo + u * 512 + c8 * 16);
        }
    }
}

// ===========================================================================
// K5: bucketed attention on HMMA, one CTA per (bh,u), 8 warps.
// Stage 1: S = Q @ K2^T (bf16x3; A/B fragment addressing = GEMM kernel).
// fp32 softmax in smem. Stage 2: O = P @ V2 (trans-ldmatrix B = permute
// kernel pattern, 256B pitch). V2 reuses K2 smem; P reuses Q smem.
// Epilogue writes g_ohi/g_olo.
// ===========================================================================
#define ASM_Q    0                  // A panels hi: [2][64][64] bf16 = 16KB
#define ASM_QLO  16384
#define ASM_K    32768              // B hi: K2 [2][128][64] 32KB / V2 [128][128] 32KB
#define ASM_KLO  65536
#define ASM_DS   98304              // fp32 [64][132]
#define ATTN_SMEM_BYTES (98304 + 64 * 132 * 4)

__global__ void __launch_bounds__(256)
attn_kernel()
{
    extern __shared__ char smb[];
    const uint32_t sbase = smem_u32(smb);
    float* ds = reinterpret_cast<float*>(smb + ASM_DS);
    const int tid  = threadIdx.x;
    const int wid  = tid >> 5, lane = tid & 31;
    const int wm2  = (wid & 1) * 32;     // 2 warps over m=64
    const int wn2  = (wid >> 1) * 32;    // 4 warps over n=128
    const size_t base = (size_t)blockIdx.x * TILE_ELEMS;

    // ---- load Q panels: [p][m][64] bf16, sw128 ----------------------------
    for (int i = tid; i < 1024; i += 256) {
        int m = i >> 4, c8 = i & 15, p = c8 >> 3;
        uint32_t off = p * 8192 + sw128((uint32_t)(m * 128 + (c8 & 7) * 16));
        size_t ga = base + m * 128 + c8 * 8;
        *reinterpret_cast<uint4*>(smb + ASM_Q   + off) = *reinterpret_cast<const uint4*>(&g_qhi[ga]);
        *reinterpret_cast<uint4*>(smb + ASM_QLO + off) = *reinterpret_cast<const uint4*>(&g_qlo[ga]);
    }
    // ---- load K2 = (kre | k) panels: [p][n=128][64] bf16, sw128 -----------
    for (int i = tid; i < 2048; i += 256) {
        int n = i >> 4, c8 = i & 15, p = c8 >> 3;
        uint32_t off = p * 16384 + sw128((uint32_t)(n * 128 + (c8 & 7) * 16));
        size_t ga = (n < 64) ? base + n * 128 + c8 * 8 : base + (n - 64) * 128 + c8 * 8;
        const __nv_bfloat16* sh = (n < 64) ? g_krehi : g_khi;
        const __nv_bfloat16* sl = (n < 64) ? g_krelo : g_klo;
        *reinterpret_cast<uint4*>(smb + ASM_K   + off) = *reinterpret_cast<const uint4*>(&sh[ga]);
        *reinterpret_cast<uint4*>(smb + ASM_KLO + off) = *reinterpret_cast<const uint4*>(&sl[ga]);
    }
    __syncthreads();

    // ---- stage 1: S = Q @ K2^T, bf16x3 ------------------------------------
    {
        float acc[2][4][4] = {};
        #pragma unroll
        for (int ks = 0; ks < 8; ks++) {
            int p = ks >> 2, km = ks & 3;
            uint32_t ah[2][4], al[2][4];
            #pragma unroll
            for (int mt = 0; mt < 2; mt++) {
                uint32_t off = p * 8192 + sw128((uint32_t)((wm2 + mt * 16 + (lane & 15)) * 128
                                                           + km * 32 + (lane >> 4) * 16));
                ldsm_x4(ah[mt], sbase + ASM_Q   + off);
                ldsm_x4(al[mt], sbase + ASM_QLO + off);
            }
            uint32_t bhf[2][4], blf[2][4];
            #pragma unroll
            for (int pp = 0; pp < 2; pp++) {
                int n = wn2 + pp * 16 + ((lane >> 4) << 3) + (lane & 7);
                uint32_t off = p * 16384 + sw128((uint32_t)(n * 128 + km * 32
                                                            + (((lane >> 3) & 1) << 4)));
                ldsm_x4(bhf[pp], sbase + ASM_K   + off);
                ldsm_x4(blf[pp], sbase + ASM_KLO + off);
            }
            #pragma unroll
            for (int mt = 0; mt < 2; mt++)
                #pragma unroll
                for (int nt = 0; nt < 4; nt++) {
                    const uint32_t* bhp = &bhf[nt >> 1][(nt & 1) * 2];
                    const uint32_t* blp = &blf[nt >> 1][(nt & 1) * 2];
                    mma_bf16(acc[mt][nt], ah[mt], bhp);
                    mma_bf16(acc[mt][nt], ah[mt], blp);
                    mma_bf16(acc[mt][nt], al[mt], bhp);
                }
        }
        const int g2 = lane >> 2, t2 = (lane & 3) * 2;
        #pragma unroll
        for (int mt = 0; mt < 2; mt++)
            #pragma unroll
            for (int nt = 0; nt < 4; nt++) {
                int col = wn2 + nt * 8 + t2;
                #pragma unroll
                for (int half = 0; half < 2; half++) {
                    int row = wm2 + mt * 16 + g2 + half * 8;
                    ds[row * 132 + col]     = acc[mt][nt][half * 2 + 0] * 0.03125f;
                    ds[row * 132 + col + 1] = acc[mt][nt][half * 2 + 1] * 0.03125f;
                }
            }
    }
    __syncthreads();

    // ---- load V2 = (vre | v) into B region: [j=128][e=128], 256B pitch ----
    for (int i = tid; i < 2048; i += 256) {
        int j = i >> 4, c8 = i & 15;
        uint32_t off = swz256((uint32_t)(j * 256 + c8 * 16));
        size_t ga = (j < 64) ? base + j * 128 + c8 * 8 : base + (j - 64) * 128 + c8 * 8;
        const __nv_bfloat16* sh = (j < 64) ? g_vrehi : g_vhi;
        const __nv_bfloat16* sl = (j < 64) ? g_vrelo : g_vlo;
        *reinterpret_cast<uint4*>(smb + ASM_K   + off) = *reinterpret_cast<const uint4*>(&sh[ga]);
        *reinterpret_cast<uint4*>(smb + ASM_KLO + off) = *reinterpret_cast<const uint4*>(&sl[ga]);
    }
    // ---- softmax rows (fp32, threads 0..63, overlapped with V2 loads) -----
    if (tid < 64) {
        float m = -INFINITY;
        for (int j = 0; j < 128; j++) m = fmaxf(m, ds[tid * 132 + j]);
        float s = 0.f;
        for (int j = 0; j < 128; j++) {
            float e = expf(ds[tid * 132 + j] - m);
            ds[tid * 132 + j] = e;
            s += e;
        }
        float inv = 1.f / s;
        for (int j = 0; j < 128; j++) ds[tid * 132 + j] *= inv;
    }
    __syncthreads();

    // ---- convert P -> hi/lo A panels (overwrite Q region) -----------------
    for (int i = tid; i < 4096; i += 256) {
        int m = i >> 6, j2 = i & 63;
        int j = j2 * 2, p = j >> 6;
        uint32_t hv, lv;
        cvt2(ds[m * 132 + j], ds[m * 132 + j + 1], hv, lv);
        uint32_t off = p * 8192 + sw128((uint32_t)(m * 128 + (j & 63) * 2));
        *reinterpret_cast<uint32_t*>(smb + ASM_Q   + off) = hv;
        *reinterpret_cast<uint32_t*>(smb + ASM_QLO + off) = lv;
    }
    __syncthreads();

    // ---- stage 2: O = P @ V2, bf16x3 (trans-ldmatrix B) -------------------
    {
        float acc[2][4][4] = {};
        #pragma unroll
        for (int ks = 0; ks < 8; ks++) {
            int p = ks >> 2, km = ks & 3;
            uint32_t ah[2][4], al[2][4];
            #pragma unroll
            for (int mt = 0; mt < 2; mt++) {
                uint32_t off = p * 8192 + sw128((uint32_t)((wm2 + mt * 16 + (lane & 15)) * 128
                                                           + km * 32 + (lane >> 4) * 16));
                ldsm_x4(ah[mt], sbase + ASM_Q   + off);
                ldsm_x4(al[mt], sbase + ASM_QLO + off);
            }
            uint32_t vhf[2][4], vlf[2][4];
            #pragma unroll
            for (int pp = 0; pp < 2; pp++) {
                int n0 = wn2 + pp * 16;
                uint32_t off = swz256((uint32_t)((ks * 16 + (lane & 15)) * 256
                                                 + (n0 + (lane >> 4) * 8) * 2));
                ldsm_x4_t(vhf[pp], sbase + ASM_K   + off);
                ldsm_x4_t(vlf[pp], sbase + ASM_KLO + off);
            }
            #pragma unroll
            for (int mt = 0; mt < 2; mt++)
                #pragma unroll
                for (int nt = 0; nt < 4; nt++) {
                    const uint32_t* bhp = &vhf[nt >> 1][(nt & 1) * 2];
                    const uint32_t* blp = &vlf[nt >> 1][(nt & 1) * 2];
                    mma_bf16(acc[mt][nt], ah[mt], bhp);
                    mma_bf16(acc[mt][nt], ah[mt], blp);
                    mma_bf16(acc[mt][nt], al[mt], bhp);
                }
        }
        const int g2 = lane >> 2, t2 = (lane & 3) * 2;
        #pragma unroll
        for (int mt = 0; mt < 2; mt++)
            #pragma unroll
            for (int nt = 0; nt < 4; nt++) {
                int col = wn2 + nt * 8 + t2;
                #pragma unroll
                for (int half = 0; half < 2; half++) {
                    int row = wm2 + mt * 16 + g2 + half * 8;
                    uint32_t hv, lv;
                    cvt2(acc[mt][nt][half * 2 + 0], acc[mt][nt][half * 2 + 1], hv, lv);
                    size_t o = base + row * 128 + col;
                    *reinterpret_cast<uint32_t*>(&g_ohi[o]) = hv;
                    *reinterpret_cast<uint32_t*>(&g_olo[o]) = lv;
                }
            }
    }
}

// ===========================================================================
extern "C" void kernel_launch(void* const* d_in, const int* in_sizes, int n_in,
                              void* d_out, int out_size)
{
    (void)in_sizes; (void)n_in; (void)out_size;
    const float* x      = (const float*)d_in[0];
    const float* w_qkv  = (const float*)d_in[1];
    const float* sort_w = (const float*)d_in[2];
    const float* w_out  = (const float*)d_in[3];
    const float* b_out  = (const float*)d_in[4];
    const float* noise  = (const float*)d_in[5];
    float* out = (float*)d_out;

    cudaFuncSetAttribute(attn_kernel, cudaFuncAttributeMaxDynamicSharedMemorySize,
                         ATTN_SMEM_BYTES);
    cudaFuncSetAttribute(mma_gemm_kernel<0>, cudaFuncAttributeMaxDynamicSharedMemorySize,
                         GEMM_SMEM_BYTES);
    cudaFuncSetAttribute(mma_gemm_kernel<1>, cudaFuncAttributeMaxDynamicSharedMemorySize,
                         GEMM_SMEM_BYTES);
    cudaFuncSetAttribute(permute_kernel, cudaFuncAttributeMaxDynamicSharedMemorySize,
                         PERM_SMEM_BYTES);

    split_kernel<<<4096, 256>>>((const float4*)x,     4194304, 0);
    split_kernel<<<3072, 256>>>((const float4*)w_qkv,  786432, 1);
    split_kernel<<<1024, 256>>>((const float4*)w_out,  262144, 2);

    mma_gemm_kernel<0><<<dim3(128, 24), 256, GEMM_SMEM_BYTES>>>(nullptr, nullptr);

    bucket_sum_kernel<<<2048, 128>>>();
    sinkhorn_kernel<<<32, 256>>>(sort_w, noise);
    permute_kernel<<<1024, 256, PERM_SMEM_BYTES>>>();
    attn_kernel<<<2048, 256, ATTN_SMEM_BYTES>>>();

    mma_gemm_kernel<1><<<dim3(128, 8), 256, GEMM_SMEM_BYTES>>>(b_out, out);
}